// round 10
// baseline (speedup 1.0000x reference)
#include <cuda_runtime.h>
#include <cuda_bf16.h>
#include <cstdint>

typedef unsigned long long ull;
typedef __nv_bfloat16 bf;

#define NB 2
#define NN 1500
#define TT 20
#define DINc 32
#define CC 128
#define RR 5
#define KKc 5
#define LL 3
#define M3 (NB*NN)
#define NP 1536
#define M3P (NB*NP)
#define PADM 1536
#define NROWT 12
#define CHUNK 64
#define NCH (PADM/CHUNK)
#define TILE_B 16384
#define BUF_B (4*TILE_B)
#define SMEM_HMMA (2*BUF_B)
#define HPV_PITCH 136
#define SMEM_HPV ((2*CC*HPV_PITCH + CC)*4)

// ---------------- scratch ----------------
__device__ float g_h[M3*CC];
__device__ bf g_hbh[M3P*CC], g_hbl[M3P*CC];
__device__ bf g_wmsh[RR*CC*CC], g_wmsl[RR*CC*CC];
__device__ float g_bqkv[3*CC];
__device__ float g_bv[LL*CC];
__device__ bf g_adj_hi[NB*RR*NN*PADM];
__device__ bf g_adj_lo[NB*RR*NN*PADM];
__device__ bf g_hwt_hi[RR*CC*NB*PADM];
__device__ bf g_hwt_lo[RR*CC*NB*PADM];
__device__ float g_part[NB*RR*NN*CC];
__device__ bf g_hdbh[M3P*CC], g_hdbl[M3P*CC];
__device__ float g_qkv[M3P*3*CC];
__device__ bf g_ovbh[M3P*CC], g_ovbl[M3P*CC];
__device__ bf g_hrbh[M3P*CC], g_hrbl[M3P*CC];
__device__ float g_hmid[M3P*CC];
// weight slabs (hi/lo)
__device__ bf g_wqh[LL*3*CC*CC], g_wql[LL*3*CC*CC];
__device__ bf g_woh[LL*CC*CC],   g_wol[LL*CC*CC];
__device__ bf g_w2h[LL*CC*CC],   g_w2l[LL*CC*CC];   // first-128-col slice of w2
__device__ bf g_wo1h[CC*CC],     g_wo1l[CC*CC];

// ---------------- helpers ----------------
__device__ __forceinline__ ull pk2(float x, float y){
  ull r; asm("mov.b64 %0,{%1,%2};" : "=l"(r) : "f"(x), "f"(y)); return r;
}
__device__ __forceinline__ void fma2(ull &c, ull a, ull b){
  asm("fma.rn.f32x2 %0, %1, %2, %0;" : "+l"(c) : "l"(a), "l"(b));
}
__device__ __forceinline__ float2 up2(ull a){
  float2 v; asm("mov.b64 {%0,%1}, %2;" : "=f"(v.x), "=f"(v.y) : "l"(a)); return v;
}
__device__ __forceinline__ float4 ld4(const float* __restrict__ p, int k, int Ke){
  float4 v = make_float4(0.f,0.f,0.f,0.f);
  if (k + 4 <= Ke) v = *(const float4*)(p + k);
  else {
    if (k   < Ke) v.x = p[k];
    if (k+1 < Ke) v.y = p[k+1];
    if (k+2 < Ke) v.z = p[k+2];
    if (k+3 < Ke) v.w = p[k+3];
  }
  return v;
}
__device__ __forceinline__ uint32_t smem_u32(const void* p){
  uint32_t a; asm("{ .reg .u64 t; cvta.to.shared.u64 t, %1; cvt.u32.u64 %0, t; }" : "=r"(a) : "l"(p));
  return a;
}
__device__ __forceinline__ void cpa16(uint32_t d, const void* s, uint32_t sz){
  asm volatile("cp.async.cg.shared.global [%0], [%1], 16, %2;" :: "r"(d), "l"(s), "r"(sz) : "memory");
}
#define CP_COMMIT() asm volatile("cp.async.commit_group;" ::: "memory")
#define CP_WAIT(n)  asm volatile("cp.async.wait_group %0;" :: "n"(n) : "memory")
__device__ __forceinline__ void ldsm4(uint32_t a, uint32_t* r){
  asm volatile("ldmatrix.sync.aligned.m8n8.x4.shared.b16 {%0,%1,%2,%3}, [%4];"
    : "=r"(r[0]), "=r"(r[1]), "=r"(r[2]), "=r"(r[3]) : "r"(a));
}
__device__ __forceinline__ void mma16816(float* c, const uint32_t* a, uint32_t b0, uint32_t b1){
  asm volatile("mma.sync.aligned.m16n8k16.row.col.f32.bf16.bf16.f32 "
    "{%0,%1,%2,%3},{%4,%5,%6,%7},{%8,%9},{%0,%1,%2,%3};"
    : "+f"(c[0]), "+f"(c[1]), "+f"(c[2]), "+f"(c[3])
    : "r"(a[0]), "r"(a[1]), "r"(a[2]), "r"(a[3]), "r"(b0), "r"(b1));
}
__device__ __forceinline__ void split_bf(float v, bf& h, bf& l){
  h = __float2bfloat16(v);
  l = __float2bfloat16(v - __bfloat162float(h));
}

// ---------------- FFMA GEMM (embed only) ----------------
#define PA 65
#define PB 132
__global__ void __launch_bounds__(256,2)
k_gemm(const float* __restrict__ A, int lda,
       const float* __restrict__ Bw, int ldb,
       float* __restrict__ C, int ldc,
       int M, int Nn, int K,
       const float* __restrict__ b1, int relu)
{
  __shared__ float As[16*PA];
  __shared__ float Bs[16*PB];
  int row0 = blockIdx.x*64, col0 = blockIdx.y*128;
  int tid = threadIdx.x;
  int arow = tid >> 2;
  int akq  = (tid & 3) << 2;
  bool aok = (row0 + arow) < M;
  const float* Arow = A + (size_t)(aok ? (row0+arow) : 0)*lda;
  int bn  = tid >> 2;
  int bkq = (tid & 3) << 2;
  int ty = tid >> 4, tx = tid & 15;

  ull acc[4][4];
#pragma unroll
  for (int i=0;i<4;i++){ acc[i][0]=0ULL; acc[i][1]=0ULL; acc[i][2]=0ULL; acc[i][3]=0ULL; }

  int nT = (K + 15) >> 4;
  for (int t=0; t<nT; t++){
    int k0 = t << 4;
    int Ke = K - k0;
    float4 av = aok ? ld4(Arow + k0, akq, Ke) : make_float4(0,0,0,0);
    As[(akq+0)*PA + arow] = av.x;
    As[(akq+1)*PA + arow] = av.y;
    As[(akq+2)*PA + arow] = av.z;
    As[(akq+3)*PA + arow] = av.w;
#pragma unroll
    for (int hh=0; hh<2; hh++){
      int n = bn + hh*64;
      int col = col0 + n;
      float4 bv = (col < Nn) ? ld4(Bw + (size_t)col*ldb + k0, bkq, Ke)
                             : make_float4(0,0,0,0);
      Bs[(bkq+0)*PB + n] = bv.x;
      Bs[(bkq+1)*PB + n] = bv.y;
      Bs[(bkq+2)*PB + n] = bv.z;
      Bs[(bkq+3)*PB + n] = bv.w;
    }
    __syncthreads();
#pragma unroll
    for (int k=0;k<16;k++){
      const float* ap = &As[k*PA + (ty<<2)];
      float a0=ap[0], a1=ap[1], a2=ap[2], a3=ap[3];
      const float4* bp4 = (const float4*)&Bs[k*PB + (tx<<3)];
      float4 b0v = bp4[0], b1v = bp4[1];
      ull p0=pk2(b0v.x,b0v.y), p1=pk2(b0v.z,b0v.w);
      ull p2=pk2(b1v.x,b1v.y), p3=pk2(b1v.z,b1v.w);
      ull ad;
      ad=pk2(a0,a0); fma2(acc[0][0],ad,p0); fma2(acc[0][1],ad,p1); fma2(acc[0][2],ad,p2); fma2(acc[0][3],ad,p3);
      ad=pk2(a1,a1); fma2(acc[1][0],ad,p0); fma2(acc[1][1],ad,p1); fma2(acc[1][2],ad,p2); fma2(acc[1][3],ad,p3);
      ad=pk2(a2,a2); fma2(acc[2][0],ad,p0); fma2(acc[2][1],ad,p1); fma2(acc[2][2],ad,p2); fma2(acc[2][3],ad,p3);
      ad=pk2(a3,a3); fma2(acc[3][0],ad,p0); fma2(acc[3][1],ad,p1); fma2(acc[3][2],ad,p2); fma2(acc[3][3],ad,p3);
    }
    __syncthreads();
  }
#pragma unroll
  for (int i=0;i<4;i++){
    int r = row0 + (ty<<2) + i;
    if (r >= M) continue;
    float* Cr = C + (size_t)r*ldc;
#pragma unroll
    for (int jp=0;jp<4;jp++){
      float2 v = up2(acc[i][jp]);
      int c0 = col0 + (tx<<3) + jp*2;
      if (c0 < Nn){
        float val = v.x + (b1 ? b1[c0] : 0.f);
        if (relu) val = fmaxf(val, 0.f);
        Cr[c0] = val;
      }
      if (c0+1 < Nn){
        float val = v.y + (b1 ? b1[c0+1] : 0.f);
        if (relu) val = fmaxf(val, 0.f);
        Cr[c0+1] = val;
      }
    }
  }
}

// ---------------- generic HMMA GEMM: out = act(A@W^T + b1 + b2) ----------------
// optional fused GroupNorm epilogue (gng != nullptr): requires gridDim.y == 1,
// relu=0; normalizes each row over 4 groups of 32 cols, writes Chi/Clo.
__global__ void __launch_bounds__(256,1)
k_hgemm(const bf* __restrict__ Ah, const bf* __restrict__ Al,
        const bf* __restrict__ Wh, const bf* __restrict__ Wl, int K,
        float* __restrict__ Cf, int ldc,
        bf* __restrict__ Chi, bf* __restrict__ Clo, int ldcb,
        const float* __restrict__ b1, const float* __restrict__ b2, int relu,
        const float* __restrict__ gng, const float* __restrict__ gnb)
{
  extern __shared__ __align__(16) char smem[];
  uint32_t sb = smem_u32(smem);
  int tid = threadIdx.x;
  int lane = tid & 31, wid = tid >> 5;
  int row0 = blockIdx.x * 128;
  int col0 = blockIdx.y * 128;

  int lr = tid >> 1, half = tid & 1;
  const bf* ah = Ah + (size_t)(row0 + lr)*K;
  const bf* al = Al + (size_t)(row0 + lr)*K;
  const bf* wh = Wh + (size_t)(col0 + lr)*K;
  const bf* wl = Wl + (size_t)(col0 + lr)*K;

  uint32_t doff[4];
#pragma unroll
  for (int j=0;j<4;j++){
    uint32_t c16 = half*4 + j;
    doff[j] = (uint32_t)lr*128u + ((c16 ^ ((uint32_t)lr & 7u)) * 16u);
  }

  int m_ = lane >> 3;
  int l7 = lane & 7;
  int wm = wid >> 1, wn = wid & 1;
  int arow = wm*32 + (m_&1)*8 + l7;
  int acb  = m_ >> 1;
  int bnp  = (m_>>1)*8 + l7;
  int bcb  = m_ & 1;

  float acc[2][8][4];
#pragma unroll
  for (int t=0;t<2;t++)
#pragma unroll
    for (int n=0;n<8;n++){ acc[t][n][0]=0.f; acc[t][n][1]=0.f; acc[t][n][2]=0.f; acc[t][n][3]=0.f; }

  int nch = K >> 6;
  {
    uint32_t base = sb;
#pragma unroll
    for (int j=0;j<4;j++){
      int moff = half*32 + j*8;
      cpa16(base + 0*TILE_B + doff[j], ah + moff, 16u);
      cpa16(base + 1*TILE_B + doff[j], al + moff, 16u);
      cpa16(base + 2*TILE_B + doff[j], wh + moff, 16u);
      cpa16(base + 3*TILE_B + doff[j], wl + moff, 16u);
    }
    CP_COMMIT();
  }

  for (int c=0; c<nch; c++){
    if (c + 1 < nch){
      uint32_t base = sb + (uint32_t)((c+1)&1)*BUF_B;
      int m0 = (c+1)*CHUNK + half*32;
#pragma unroll
      for (int j=0;j<4;j++){
        int moff = m0 + j*8;
        cpa16(base + 0*TILE_B + doff[j], ah + moff, 16u);
        cpa16(base + 1*TILE_B + doff[j], al + moff, 16u);
        cpa16(base + 2*TILE_B + doff[j], wh + moff, 16u);
        cpa16(base + 3*TILE_B + doff[j], wl + moff, 16u);
      }
      CP_COMMIT();
      CP_WAIT(1);
    } else {
      CP_WAIT(0);
    }
    __syncthreads();

    uint32_t bA = sb + (uint32_t)(c&1)*BUF_B;
#pragma unroll
    for (int ks=0; ks<4; ks++){
      uint32_t ahr[2][4], alr[2][4];
#pragma unroll
      for (int t=0;t<2;t++){
        uint32_t aoff = (uint32_t)(arow + t*16)*128u + ((((uint32_t)(ks*2 + acb)) ^ (uint32_t)l7) * 16u);
        ldsm4(bA + 0*TILE_B + aoff, ahr[t]);
        ldsm4(bA + 1*TILE_B + aoff, alr[t]);
      }
#pragma unroll
      for (int p=0;p<4;p++){
        uint32_t bhr[4], blr[4];
        uint32_t nB = (uint32_t)(wn*64 + p*16 + bnp);
        uint32_t boff = nB*128u + ((((uint32_t)(ks*2 + bcb)) ^ (uint32_t)l7) * 16u);
        ldsm4(bA + 2*TILE_B + boff, bhr);
        ldsm4(bA + 3*TILE_B + boff, blr);
#pragma unroll
        for (int t=0;t<2;t++){
          mma16816(acc[t][2*p+0], ahr[t], bhr[0], bhr[1]);
          mma16816(acc[t][2*p+0], ahr[t], blr[0], blr[1]);
          mma16816(acc[t][2*p+0], alr[t], bhr[0], bhr[1]);
          mma16816(acc[t][2*p+1], ahr[t], bhr[2], bhr[3]);
          mma16816(acc[t][2*p+1], ahr[t], blr[2], blr[3]);
          mma16816(acc[t][2*p+1], alr[t], bhr[2], bhr[3]);
        }
      }
    }
    __syncthreads();
  }

  if (gng){
    // ---- fused GroupNorm epilogue ----
    float* st = (float*)smem;   // [128][129]
#pragma unroll
    for (int t=0;t<2;t++){
      int rb = wm*32 + t*16 + (lane>>2);
#pragma unroll
      for (int n=0;n<8;n++){
        int cl = wn*64 + n*8 + (lane&3)*2;
        float bs0 = b1 ? b1[cl]   : 0.f;
        float bs1 = b1 ? b1[cl+1] : 0.f;
#pragma unroll
        for (int hrow=0;hrow<2;hrow++){
          int r = rb + hrow*8;
          st[r*129 + cl]     = acc[t][n][hrow*2+0] + bs0;
          st[r*129 + cl + 1] = acc[t][n][hrow*2+1] + bs1;
        }
      }
    }
    __syncthreads();
    int row = tid >> 1, hh = tid & 1;
#pragma unroll
    for (int g=0; g<2; g++){
      int cb = hh*64 + g*32;
      const float* sr = st + row*129 + cb;
      float mu = 0.f;
#pragma unroll
      for (int i=0;i<32;i++) mu += sr[i];
      mu *= (1.0f/32.0f);
      float var = 0.f;
#pragma unroll
      for (int i=0;i<32;i++){ float d = sr[i]-mu; var += d*d; }
      var *= (1.0f/32.0f);
      float inv = rsqrtf(var + 1e-5f);
      size_t ob0 = (size_t)(row0+row)*ldcb + cb;
#pragma unroll
      for (int i8=0; i8<4; i8++){
        uint32_t hp_[4], lp_[4];
#pragma unroll
        for (int q=0;q<4;q++){
          int i = i8*8 + q*2;
          float y0 = (sr[i]-mu)*inv*gng[cb+i]   + gnb[cb+i];
          float y1 = (sr[i+1]-mu)*inv*gng[cb+i+1] + gnb[cb+i+1];
          bf h0,l0,h1,l1;
          split_bf(y0,h0,l0); split_bf(y1,h1,l1);
          hp_[q] = ((uint32_t)__bfloat16_as_ushort(h1) << 16) | __bfloat16_as_ushort(h0);
          lp_[q] = ((uint32_t)__bfloat16_as_ushort(l1) << 16) | __bfloat16_as_ushort(l0);
        }
        *(uint4*)(Chi + ob0 + i8*8) = make_uint4(hp_[0],hp_[1],hp_[2],hp_[3]);
        *(uint4*)(Clo + ob0 + i8*8) = make_uint4(lp_[0],lp_[1],lp_[2],lp_[3]);
      }
    }
    return;
  }

#pragma unroll
  for (int t=0;t<2;t++){
    int rb = row0 + wm*32 + t*16 + (lane>>2);
#pragma unroll
    for (int n=0;n<8;n++){
      int cl = wn*64 + n*8 + (lane&3)*2;
      int cg = col0 + cl;
      float bsum0 = (b1 ? b1[cg]   : 0.f) + (b2 ? b2[cg]   : 0.f);
      float bsum1 = (b1 ? b1[cg+1] : 0.f) + (b2 ? b2[cg+1] : 0.f);
#pragma unroll
      for (int hrow=0;hrow<2;hrow++){
        int r = rb + hrow*8;
        float v0 = acc[t][n][hrow*2+0] + bsum0;
        float v1 = acc[t][n][hrow*2+1] + bsum1;
        if (relu){ v0 = fmaxf(v0, 0.f); v1 = fmaxf(v1, 0.f); }
        if (Cf){
          float2 vv; vv.x = v0; vv.y = v1;
          *(float2*)(Cf + (size_t)r*ldc + cg) = vv;
        }
        if (Chi){
          bf h0,l0,h1,l1;
          split_bf(v0,h0,l0); split_bf(v1,h1,l1);
          size_t o = (size_t)r*ldcb + cg;
          Chi[o] = h0; Chi[o+1] = h1;
          Clo[o] = l0; Clo[o+1] = l1;
        }
      }
    }
  }
}

// ---------------- adjacency HMMA ----------------
__global__ void __launch_bounds__(256,1)
k_hmma_diff(float* __restrict__ part)
{
  extern __shared__ __align__(16) char smem[];
  uint32_t sb = smem_u32(smem);
  int tid = threadIdx.x;
  int lane = tid & 31, wid = tid >> 5;
  int z = blockIdx.z;
  int b = z / RR, r = z - b*RR;
  int row0 = blockIdx.x * 128;

  int lr = tid >> 1, half = tid & 1;
  bool rowok = (row0 + lr) < NN;
  const bf* ah = g_adj_hi + ((size_t)z*NN + (rowok ? (row0+lr) : 0))*PADM;
  const bf* al = g_adj_lo + ((size_t)z*NN + (rowok ? (row0+lr) : 0))*PADM;
  const bf* bh = g_hwt_hi + ((size_t)((r*CC + lr)*2 + b))*PADM;
  const bf* bl = g_hwt_lo + ((size_t)((r*CC + lr)*2 + b))*PADM;
  uint32_t asz = rowok ? 16u : 0u;

  uint32_t doff[4];
#pragma unroll
  for (int j=0;j<4;j++){
    uint32_t c16 = half*4 + j;
    doff[j] = (uint32_t)lr*128u + ((c16 ^ ((uint32_t)lr & 7u)) * 16u);
  }

  int m_ = lane >> 3;
  int l7 = lane & 7;
  int wm = wid >> 1, wn = wid & 1;
  int arow = wm*32 + (m_&1)*8 + l7;
  int acb  = m_ >> 1;
  int bnp  = (m_>>1)*8 + l7;
  int bcb  = m_ & 1;

  float acc[2][8][4];
#pragma unroll
  for (int t=0;t<2;t++)
#pragma unroll
    for (int n=0;n<8;n++){ acc[t][n][0]=0.f; acc[t][n][1]=0.f; acc[t][n][2]=0.f; acc[t][n][3]=0.f; }

  {
    uint32_t base = sb;
#pragma unroll
    for (int j=0;j<4;j++){
      int moff = half*32 + j*8;
      cpa16(base + 0*TILE_B + doff[j], ah + moff, asz);
      cpa16(base + 1*TILE_B + doff[j], al + moff, asz);
      cpa16(base + 2*TILE_B + doff[j], bh + moff, 16u);
      cpa16(base + 3*TILE_B + doff[j], bl + moff, 16u);
    }
    CP_COMMIT();
  }

  for (int c=0; c<NCH; c++){
    if (c + 1 < NCH){
      uint32_t base = sb + (uint32_t)((c+1)&1)*BUF_B;
      int m0 = (c+1)*CHUNK + half*32;
#pragma unroll
      for (int j=0;j<4;j++){
        int moff = m0 + j*8;
        cpa16(base + 0*TILE_B + doff[j], ah + moff, asz);
        cpa16(base + 1*TILE_B + doff[j], al + moff, asz);
        cpa16(base + 2*TILE_B + doff[j], bh + moff, 16u);
        cpa16(base + 3*TILE_B + doff[j], bl + moff, 16u);
      }
      CP_COMMIT();
      CP_WAIT(1);
    } else {
      CP_WAIT(0);
    }
    __syncthreads();

    uint32_t bA = sb + (uint32_t)(c&1)*BUF_B;
#pragma unroll
    for (int ks=0; ks<4; ks++){
      uint32_t ahr[2][4], alr[2][4];
#pragma unroll
      for (int t=0;t<2;t++){
        uint32_t aoff = (uint32_t)(arow + t*16)*128u + ((((uint32_t)(ks*2 + acb)) ^ (uint32_t)l7) * 16u);
        ldsm4(bA + 0*TILE_B + aoff, ahr[t]);
        ldsm4(bA + 1*TILE_B + aoff, alr[t]);
      }
#pragma unroll
      for (int p=0;p<4;p++){
        uint32_t bhr[4], blr[4];
        uint32_t nB = (uint32_t)(wn*64 + p*16 + bnp);
        uint32_t boff = nB*128u + ((((uint32_t)(ks*2 + bcb)) ^ (uint32_t)l7) * 16u);
        ldsm4(bA + 2*TILE_B + boff, bhr);
        ldsm4(bA + 3*TILE_B + boff, blr);
#pragma unroll
        for (int t=0;t<2;t++){
          mma16816(acc[t][2*p+0], ahr[t], bhr[0], bhr[1]);
          mma16816(acc[t][2*p+0], ahr[t], blr[0], blr[1]);
          mma16816(acc[t][2*p+0], alr[t], bhr[0], bhr[1]);
          mma16816(acc[t][2*p+1], ahr[t], bhr[2], bhr[3]);
          mma16816(acc[t][2*p+1], ahr[t], blr[2], blr[3]);
          mma16816(acc[t][2*p+1], alr[t], bhr[2], bhr[3]);
        }
      }
    }
    __syncthreads();
  }

  float* pz = part + (size_t)z*NN*CC;
#pragma unroll
  for (int t=0;t<2;t++){
    int r0 = row0 + wm*32 + t*16 + (lane>>2);
#pragma unroll
    for (int n=0;n<8;n++){
      int c0 = wn*64 + n*8 + (lane&3)*2;
      if (r0 < NN){
        float2 v; v.x = acc[t][n][0]; v.y = acc[t][n][1];
        *(float2*)(pz + (size_t)r0*CC + c0) = v;
      }
      if (r0 + 8 < NN){
        float2 v; v.x = acc[t][n][2]; v.y = acc[t][n][3];
        *(float2*)(pz + (size_t)(r0+8)*CC + c0) = v;
      }
    }
  }
}

// ---------------- elementwise / conversion ----------------
#define QTR (CC*CC)              // 16384
__global__ void k_initzero(){
  int idx = blockIdx.x*256 + threadIdx.x;
  const int per = M3P*CC/8;
  if (idx >= 8*per) return;
  int a = idx / per, off = idx - a*per;
  float4* p;
  switch(a){
    case 0: p = (float4*)g_hdbh; break;
    case 1: p = (float4*)g_hdbl; break;
    case 2: p = (float4*)g_ovbh; break;
    case 3: p = (float4*)g_ovbl; break;
    case 4: p = (float4*)g_hrbh; break;
    case 5: p = (float4*)g_hrbl; break;
    case 6: p = (float4*)g_hbh;  break;
    default: p = (float4*)g_hbl; break;
  }
  p[off] = make_float4(0.f,0.f,0.f,0.f);
}

__global__ void k_cvtw(const float* __restrict__ qw, const float* __restrict__ kw,
                       const float* __restrict__ vw, const float* __restrict__ ow,
                       const float* __restrict__ w2, const float* __restrict__ ow1){
  int i = blockIdx.x*256 + threadIdx.x;
  if (i >= 16*QTR) return;
  float v; bf* dh; bf* dl; int di;
  if (i < 9*QTR){
    int l = i / (3*QTR);
    int rem = i - l*3*QTR;
    int which = rem / QTR;
    int within = rem - which*QTR;
    const float* src = (which==0) ? qw : (which==1) ? kw : vw;
    v = src[(size_t)l*QTR + within];
    dh = g_wqh; dl = g_wql; di = i;
  } else if (i < 12*QTR){
    int j = i - 9*QTR;
    v = ow[j];
    dh = g_woh; dl = g_wol; di = j;
  } else if (i < 15*QTR){
    int j = i - 12*QTR;
    int lc = j >> 7, k = j & 127;
    v = w2[(size_t)lc*(2*CC) + k];
    dh = g_w2h; dl = g_w2l; di = j;
  } else {
    int j = i - 15*QTR;
    v = ow1[j];
    dh = g_wo1h; dl = g_wo1l; di = j;
  }
  bf h, lo; split_bf(v, h, lo);
  dh[di] = h; dl[di] = lo;
}

__global__ void k_adjconv(const float* __restrict__ adj){
  int row = blockIdx.x;
  const float* src = adj + (size_t)row*NN;
  bf* dh = g_adj_hi + (size_t)row*PADM;
  bf* dl = g_adj_lo + (size_t)row*PADM;
#pragma unroll
  for (int t=0; t<PADM/256; t++){
    int m = threadIdx.x + t*256;
    float v = (m < NN) ? src[m] : 0.f;
    bf h,l; split_bf(v,h,l);
    dh[m] = h; dl[m] = l;
  }
}

__global__ void k_wmsb(const float* __restrict__ tr, const float* __restrict__ cw,
                       const float* __restrict__ qb, const float* __restrict__ kb,
                       const float* __restrict__ vb, int l)
{
  int idx = blockIdx.x*256 + threadIdx.x;
  if (idx < RR*CC*CC){
    int r = idx >> 14;
    int oc = idx & 16383;
    const float* base = tr + (((size_t)(l*RR + r)*KKc) << 14) + oc;
    float s = 0.f;
#pragma unroll
    for (int k=0;k<KKc;k++) s += base[(size_t)k << 14];
    float v = cw[l*RR + r] * s * (1.0f/KKc);
    bf h,lo; split_bf(v,h,lo);
    g_wmsh[idx] = h; g_wmsl[idx] = lo;
  } else {
    int i = idx - RR*CC*CC;
    if (i < 3*CC){
      int which = i >> 7, c = i & 127;
      const float* s = (which==0) ? qb : (which==1) ? kb : vb;
      g_bqkv[i] = s[l*CC + c];
    }
  }
}

// h_prime recurrence (row-constant): smem-staged, 1024 threads, coalesced
__global__ void __launch_bounds__(1024,1)
k_hpvec(const float* __restrict__ w1, const float* __restrict__ b1,
        const float* __restrict__ eb1, const float* __restrict__ w2,
        const float* __restrict__ b2, const float* __restrict__ eb2)
{
  extern __shared__ float sw[];
  float* s1 = sw;                    // [CC][HPV_PITCH]
  float* s2 = sw + CC*HPV_PITCH;     // [CC][HPV_PITCH]
  float* hp = sw + 2*CC*HPV_PITCH;   // [CC]
  int tid = threadIdx.x;
  if (tid < CC) hp[tid] = 0.f;
  int c = tid >> 3, g = tid & 7;
  for (int l=0; l<LL; l++){
    __syncthreads();
    for (int j = tid; j < CC*CC; j += 1024){
      int cc = j >> 7, k = j & 127;
      s1[cc*HPV_PITCH + k] = w1[(size_t)l*QTR + j];
      s2[cc*HPV_PITCH + k] = w2[((size_t)(l*CC)+cc)*(2*CC) + CC + k];
    }
    __syncthreads();
    float nh = 0.f, bv = 0.f;
#pragma unroll
    for (int kk=0; kk<16; kk++){
      int k = kk*8 + g;
      float hv = hp[k];
      nh += hv * s1[c*HPV_PITCH + k];
      bv += hv * s2[c*HPV_PITCH + k];
    }
#pragma unroll
    for (int o=4;o>0;o>>=1){
      nh += __shfl_xor_sync(0xffffffffu, nh, o);
      bv += __shfl_xor_sync(0xffffffffu, bv, o);
    }
    __syncthreads();
    if (g == 0){
      g_bv[l*CC+c] = bv + b2[l*CC+c] + eb2[l*CC+c];
      hp[c] = fmaxf(nh + b1[l*CC+c] + eb1[l*CC+c], 0.f);
    }
  }
}

__global__ void k_cvtpad(){
  int i = blockIdx.x*256 + threadIdx.x;
  if (i >= M3*CC) return;
  int m = i / CC, c = i - m*CC;
  int b = m / NN, mm = m - b*NN;
  bf h,l; split_bf(g_h[i],h,l);
  size_t o = (size_t)(b*NP + mm)*CC + c;
  g_hbh[o] = h; g_hbl[o] = l;
}

__global__ void k_reduce(const float* __restrict__ convb, int l)
{
  int idx = blockIdx.x*256 + threadIdx.x;
  if (idx >= M3*CC) return;
  int b = idx / (NN*CC);
  int in = idx - b*NN*CC;
  int n = in / CC, c = in - n*CC;
  const float* p = g_part + (size_t)b*RR*NN*CC + in;
  float s = convb[l];
#pragma unroll
  for (int j=0;j<RR;j++) s += p[(size_t)j*NN*CC];
  s = fmaxf(s, 0.f);
  bf h,lo; split_bf(s,h,lo);
  size_t o = (size_t)(b*NP + n)*CC + c;
  g_hdbh[o] = h; g_hdbl[o] = lo;
}

__global__ void k_ret()
{
  int m = blockIdx.x, c = threadIdx.x;
  int b = m / NN;
  size_t mp = (size_t)(b*NP + (m - b*NN));
  const float* bp = g_qkv + mp*384;
  float q = bp[c], kk = bp[128+c], v = bp[256+c];
  float s = q*kk;
#pragma unroll
  for (int o=16;o>0;o>>=1) s += __shfl_xor_sync(0xffffffffu, s, o);
  float ov = s*v;
  bf h,lo; split_bf(ov,h,lo);
  g_ovbh[mp*128 + c] = h; g_ovbl[mp*128 + c] = lo;
}

__global__ void k_out2(const float* __restrict__ w, const float* __restrict__ bb,
                       float* __restrict__ out)
{
  int row = blockIdx.x, c = threadIdx.x;
  int b = row / NN;
  size_t mp = (size_t)(b*NP + (row - b*NN));
  float x = g_hmid[mp*128 + c];
  float s0 = x * w[c];
  float s1 = x * w[128 + c];
#pragma unroll
  for (int o=16;o>0;o>>=1){
    s0 += __shfl_xor_sync(0xffffffffu, s0, o);
    s1 += __shfl_xor_sync(0xffffffffu, s1, o);
  }
  __shared__ float sm[2][4];
  int wid = c >> 5;
  if ((c & 31) == 0){ sm[0][wid] = s0; sm[1][wid] = s1; }
  __syncthreads();
  if (c == 0) out[row*2 + 0] = sm[0][0]+sm[0][1]+sm[0][2]+sm[0][3] + bb[0];
  if (c == 1) out[row*2 + 1] = sm[1][0]+sm[1][1]+sm[1][2]+sm[1][3] + bb[1];
}

// ---------------- host ----------------
extern "C" void kernel_launch(void* const* d_in, const int* in_sizes, int n_in,
                              void* d_out, int out_size)
{
  (void)in_sizes; (void)n_in; (void)out_size;
  const float* x     = (const float*)d_in[0];
  const float* adj   = (const float*)d_in[1];
  const float* emb_w = (const float*)d_in[2];
  const float* emb_b = (const float*)d_in[3];
  const float* tr    = (const float*)d_in[5];
  const float* cw    = (const float*)d_in[6];
  const float* cb    = (const float*)d_in[7];
  const float* qw    = (const float*)d_in[8];
  const float* qb    = (const float*)d_in[9];
  const float* kw    = (const float*)d_in[10];
  const float* kb    = (const float*)d_in[11];
  const float* vw    = (const float*)d_in[12];
  const float* vb    = (const float*)d_in[13];
  const float* ow    = (const float*)d_in[14];
  const float* ob    = (const float*)d_in[15];
  const float* gg    = (const float*)d_in[16];
  const float* gb    = (const float*)d_in[17];
  const float* w1    = (const float*)d_in[18];
  const float* b1    = (const float*)d_in[19];
  const float* eb1   = (const float*)d_in[20];
  const float* w2    = (const float*)d_in[21];
  const float* b2    = (const float*)d_in[22];
  const float* eb2   = (const float*)d_in[23];
  const float* ow1   = (const float*)d_in[24];
  const float* ob1   = (const float*)d_in[25];
  const float* ow2   = (const float*)d_in[26];
  const float* ob2   = (const float*)d_in[27];
  float* out = (float*)d_out;

  float *p_part, *p_qkv, *p_hmid, *p_bqkv, *p_bv;
  bf *p_hbh,*p_hbl,*p_hdbh,*p_hdbl,*p_ovbh,*p_ovbl,*p_hrbh,*p_hrbl;
  bf *p_wqh,*p_wql,*p_woh,*p_wol,*p_w2h,*p_w2l,*p_wo1h,*p_wo1l,*p_wmsh,*p_wmsl;
  bf *p_hwth,*p_hwtl;
  float* p_h;
  cudaGetSymbolAddress((void**)&p_h,    g_h);
  cudaGetSymbolAddress((void**)&p_part, g_part);
  cudaGetSymbolAddress((void**)&p_qkv,  g_qkv);
  cudaGetSymbolAddress((void**)&p_hmid, g_hmid);
  cudaGetSymbolAddress((void**)&p_bqkv, g_bqkv);
  cudaGetSymbolAddress((void**)&p_bv,   g_bv);
  cudaGetSymbolAddress((void**)&p_hbh,  g_hbh);  cudaGetSymbolAddress((void**)&p_hbl,  g_hbl);
  cudaGetSymbolAddress((void**)&p_hdbh, g_hdbh); cudaGetSymbolAddress((void**)&p_hdbl, g_hdbl);
  cudaGetSymbolAddress((void**)&p_ovbh, g_ovbh); cudaGetSymbolAddress((void**)&p_ovbl, g_ovbl);
  cudaGetSymbolAddress((void**)&p_hrbh, g_hrbh); cudaGetSymbolAddress((void**)&p_hrbl, g_hrbl);
  cudaGetSymbolAddress((void**)&p_wqh,  g_wqh);  cudaGetSymbolAddress((void**)&p_wql,  g_wql);
  cudaGetSymbolAddress((void**)&p_woh,  g_woh);  cudaGetSymbolAddress((void**)&p_wol,  g_wol);
  cudaGetSymbolAddress((void**)&p_w2h,  g_w2h);  cudaGetSymbolAddress((void**)&p_w2l,  g_w2l);
  cudaGetSymbolAddress((void**)&p_wo1h, g_wo1h); cudaGetSymbolAddress((void**)&p_wo1l, g_wo1l);
  cudaGetSymbolAddress((void**)&p_wmsh, g_wmsh); cudaGetSymbolAddress((void**)&p_wmsl, g_wmsl);
  cudaGetSymbolAddress((void**)&p_hwth, g_hwt_hi); cudaGetSymbolAddress((void**)&p_hwtl, g_hwt_lo);

  cudaFuncSetAttribute(k_hmma_diff, cudaFuncAttributeMaxDynamicSharedMemorySize, SMEM_HMMA);
  cudaFuncSetAttribute(k_hgemm,     cudaFuncAttributeMaxDynamicSharedMemorySize, SMEM_HMMA);
  cudaFuncSetAttribute(k_hpvec,     cudaFuncAttributeMaxDynamicSharedMemorySize, SMEM_HPV);

  dim3 blk(256);
  const int GRT = M3P/128;  // 24

  k_initzero<<<(8*(M3P*CC/8) + 255)/256, 256>>>();
  k_adjconv<<<NB*RR*NN, 256>>>(adj);
  k_cvtw<<<(16*QTR + 255)/256, 256>>>(qw, kw, vw, ow, w2, ow1);
  k_hpvec<<<1, 1024, SMEM_HPV>>>(w1, b1, eb1, w2, b2, eb2);

  k_gemm<<<dim3((M3+63)/64,1,1), blk>>>(x + (TT-1)*DINc, TT*DINc, emb_w, DINc,
                                        p_h, CC, M3, CC, DINc, emb_b, 0);
  k_cvtpad<<<(M3*CC + 255)/256, 256>>>();

  for (int l = 0; l < LL; l++){
    k_wmsb<<<(RR*CC*CC + 3*CC + 255)/256, 256>>>(tr, cw, qb, kb, vb, l);

    // hwt[(o*2+b)][m'] = (wms @ h^T) written directly as bf hi/lo (ldcb = 3072)
    k_hgemm<<<dim3(RR, GRT, 1), blk, SMEM_HMMA>>>(p_wmsh, p_wmsl, p_hbh, p_hbl, CC,
                                                  nullptr, 0, p_hwth, p_hwtl, M3P,
                                                  nullptr, nullptr, 0, nullptr, nullptr);
    k_hmma_diff<<<dim3(NROWT,1,NB*RR), blk, SMEM_HMMA>>>(p_part);
    k_reduce<<<(M3*CC + 255)/256, 256>>>(cb, l);

    k_hgemm<<<dim3(GRT,3,1), blk, SMEM_HMMA>>>(p_hdbh, p_hdbl,
                                               p_wqh + (size_t)l*3*QTR, p_wql + (size_t)l*3*QTR, CC,
                                               p_qkv, 3*CC, nullptr, nullptr, 0,
                                               p_bqkv, nullptr, 0, nullptr, nullptr);
    k_ret<<<M3, 128>>>();
    // obf = ov @ ow^T + ob, then fused GroupNorm -> hrb (bf hi/lo)
    k_hgemm<<<dim3(GRT,1,1), blk, SMEM_HMMA>>>(p_ovbh, p_ovbl,
                                               p_woh + (size_t)l*QTR, p_wol + (size_t)l*QTR, CC,
                                               nullptr, 0, p_hrbh, p_hrbl, CC,
                                               ob + l*CC, nullptr, 0,
                                               gg + l*CC, gb + l*CC);
    // h = relu(hr @ w2[:, :128]^T + bv_l)
    k_hgemm<<<dim3(GRT,1,1), blk, SMEM_HMMA>>>(p_hrbh, p_hrbl,
                                               p_w2h + (size_t)l*QTR, p_w2l + (size_t)l*QTR, CC,
                                               nullptr, 0, p_hbh, p_hbl, CC,
                                               p_bv + l*CC, nullptr, 1, nullptr, nullptr);
  }

  k_hgemm<<<dim3(GRT,1,1), blk, SMEM_HMMA>>>(p_hbh, p_hbl, p_wo1h, p_wo1l, CC,
                                             p_hmid, CC, nullptr, nullptr, 0,
                                             ob1, nullptr, 1, nullptr, nullptr);
  k_out2<<<M3, 128>>>(ow2, ob2, out);
}

// round 11
// speedup vs baseline: 1.0151x; 1.0151x over previous
#include <cuda_runtime.h>
#include <cuda_bf16.h>
#include <cstdint>

typedef unsigned long long ull;
typedef __nv_bfloat16 bf;

#define NB 2
#define NN 1500
#define TT 20
#define DINc 32
#define CC 128
#define RR 5
#define KKc 5
#define LL 3
#define M3 (NB*NN)
#define NP 1536
#define M3P (NB*NP)
#define PADM 1536
#define NROWT 12
#define CHUNK 64
#define NCH (PADM/CHUNK)
#define TILE_B 16384
#define BUF_B (4*TILE_B)
#define SMEM_HMMA (2*BUF_B)
#define HPV_PITCH 136
#define SMEM_HPV ((2*CC*HPV_PITCH + CC)*4)
#define QTR (CC*CC)

// ---------------- scratch ----------------
__device__ bf g_hbh[M3P*CC], g_hbl[M3P*CC];
__device__ bf g_wmsh[LL*RR*CC*CC], g_wmsl[LL*RR*CC*CC];
__device__ float g_bqkv[LL*3*CC];
__device__ float g_bv[LL*CC];
__device__ bf g_adj_hi[NB*RR*NN*PADM];
__device__ bf g_adj_lo[NB*RR*NN*PADM];
__device__ bf g_hwt_hi[RR*CC*NB*PADM];
__device__ bf g_hwt_lo[RR*CC*NB*PADM];
__device__ float g_part[NB*RR*NN*CC];
__device__ bf g_hdbh[M3P*CC], g_hdbl[M3P*CC];
__device__ float g_qkv[M3P*3*CC];
__device__ bf g_ovbh[M3P*CC], g_ovbl[M3P*CC];
__device__ bf g_hrbh[M3P*CC], g_hrbl[M3P*CC];
__device__ float g_hmid[M3P*CC];
// weight slabs (hi/lo)
__device__ bf g_wqh[LL*3*CC*CC], g_wql[LL*3*CC*CC];
__device__ bf g_woh[LL*CC*CC],   g_wol[LL*CC*CC];
__device__ bf g_w2h[LL*CC*CC],   g_w2l[LL*CC*CC];   // first-128-col slice of w2
__device__ bf g_wo1h[CC*CC],     g_wo1l[CC*CC];

// ---------------- helpers ----------------
__device__ __forceinline__ ull pk2(float x, float y){
  ull r; asm("mov.b64 %0,{%1,%2};" : "=l"(r) : "f"(x), "f"(y)); return r;
}
__device__ __forceinline__ void fma2(ull &c, ull a, ull b){
  asm("fma.rn.f32x2 %0, %1, %2, %0;" : "+l"(c) : "l"(a), "l"(b));
}
__device__ __forceinline__ float2 up2(ull a){
  float2 v; asm("mov.b64 {%0,%1}, %2;" : "=f"(v.x), "=f"(v.y) : "l"(a)); return v;
}
__device__ __forceinline__ float4 ld4(const float* __restrict__ p, int k, int Ke){
  float4 v = make_float4(0.f,0.f,0.f,0.f);
  if (k + 4 <= Ke) v = *(const float4*)(p + k);
  else {
    if (k   < Ke) v.x = p[k];
    if (k+1 < Ke) v.y = p[k+1];
    if (k+2 < Ke) v.z = p[k+2];
    if (k+3 < Ke) v.w = p[k+3];
  }
  return v;
}
__device__ __forceinline__ uint32_t smem_u32(const void* p){
  uint32_t a; asm("{ .reg .u64 t; cvta.to.shared.u64 t, %1; cvt.u32.u64 %0, t; }" : "=r"(a) : "l"(p));
  return a;
}
__device__ __forceinline__ void cpa16(uint32_t d, const void* s, uint32_t sz){
  asm volatile("cp.async.cg.shared.global [%0], [%1], 16, %2;" :: "r"(d), "l"(s), "r"(sz) : "memory");
}
#define CP_COMMIT() asm volatile("cp.async.commit_group;" ::: "memory")
#define CP_WAIT(n)  asm volatile("cp.async.wait_group %0;" :: "n"(n) : "memory")
__device__ __forceinline__ void ldsm4(uint32_t a, uint32_t* r){
  asm volatile("ldmatrix.sync.aligned.m8n8.x4.shared.b16 {%0,%1,%2,%3}, [%4];"
    : "=r"(r[0]), "=r"(r[1]), "=r"(r[2]), "=r"(r[3]) : "r"(a));
}
__device__ __forceinline__ void mma16816(float* c, const uint32_t* a, uint32_t b0, uint32_t b1){
  asm volatile("mma.sync.aligned.m16n8k16.row.col.f32.bf16.bf16.f32 "
    "{%0,%1,%2,%3},{%4,%5,%6,%7},{%8,%9},{%0,%1,%2,%3};"
    : "+f"(c[0]), "+f"(c[1]), "+f"(c[2]), "+f"(c[3])
    : "r"(a[0]), "r"(a[1]), "r"(a[2]), "r"(a[3]), "r"(b0), "r"(b1));
}
__device__ __forceinline__ void split_bf(float v, bf& h, bf& l){
  h = __float2bfloat16(v);
  l = __float2bfloat16(v - __bfloat162float(h));
}

// ---------------- FFMA GEMM (embed only): writes padded bf hi/lo ----------------
#define PA 65
#define PB 132
__global__ void __launch_bounds__(256,2)
k_gemm(const float* __restrict__ A, int lda,
       const float* __restrict__ Bw, int ldb,
       bf* __restrict__ Chi, bf* __restrict__ Clo,
       int M, int Nn, int K,
       const float* __restrict__ b1)
{
  __shared__ float As[16*PA];
  __shared__ float Bs[16*PB];
  int row0 = blockIdx.x*64, col0 = 0;
  int tid = threadIdx.x;
  int arow = tid >> 2;
  int akq  = (tid & 3) << 2;
  bool aok = (row0 + arow) < M;
  const float* Arow = A + (size_t)(aok ? (row0+arow) : 0)*lda;
  int bn  = tid >> 2;
  int bkq = (tid & 3) << 2;
  int ty = tid >> 4, tx = tid & 15;

  ull acc[4][4];
#pragma unroll
  for (int i=0;i<4;i++){ acc[i][0]=0ULL; acc[i][1]=0ULL; acc[i][2]=0ULL; acc[i][3]=0ULL; }

  int nT = (K + 15) >> 4;
  for (int t=0; t<nT; t++){
    int k0 = t << 4;
    int Ke = K - k0;
    float4 av = aok ? ld4(Arow + k0, akq, Ke) : make_float4(0,0,0,0);
    As[(akq+0)*PA + arow] = av.x;
    As[(akq+1)*PA + arow] = av.y;
    As[(akq+2)*PA + arow] = av.z;
    As[(akq+3)*PA + arow] = av.w;
#pragma unroll
    for (int hh=0; hh<2; hh++){
      int n = bn + hh*64;
      int col = col0 + n;
      float4 bv = (col < Nn) ? ld4(Bw + (size_t)col*ldb + k0, bkq, Ke)
                             : make_float4(0,0,0,0);
      Bs[(bkq+0)*PB + n] = bv.x;
      Bs[(bkq+1)*PB + n] = bv.y;
      Bs[(bkq+2)*PB + n] = bv.z;
      Bs[(bkq+3)*PB + n] = bv.w;
    }
    __syncthreads();
#pragma unroll
    for (int k=0;k<16;k++){
      const float* ap = &As[k*PA + (ty<<2)];
      float a0=ap[0], a1=ap[1], a2=ap[2], a3=ap[3];
      const float4* bp4 = (const float4*)&Bs[k*PB + (tx<<3)];
      float4 b0v = bp4[0], b1v = bp4[1];
      ull p0=pk2(b0v.x,b0v.y), p1=pk2(b0v.z,b0v.w);
      ull p2=pk2(b1v.x,b1v.y), p3=pk2(b1v.z,b1v.w);
      ull ad;
      ad=pk2(a0,a0); fma2(acc[0][0],ad,p0); fma2(acc[0][1],ad,p1); fma2(acc[0][2],ad,p2); fma2(acc[0][3],ad,p3);
      ad=pk2(a1,a1); fma2(acc[1][0],ad,p0); fma2(acc[1][1],ad,p1); fma2(acc[1][2],ad,p2); fma2(acc[1][3],ad,p3);
      ad=pk2(a2,a2); fma2(acc[2][0],ad,p0); fma2(acc[2][1],ad,p1); fma2(acc[2][2],ad,p2); fma2(acc[2][3],ad,p3);
      ad=pk2(a3,a3); fma2(acc[3][0],ad,p0); fma2(acc[3][1],ad,p1); fma2(acc[3][2],ad,p2); fma2(acc[3][3],ad,p3);
    }
    __syncthreads();
  }
#pragma unroll
  for (int i=0;i<4;i++){
    int r = row0 + (ty<<2) + i;
    if (r >= M) continue;
    int bb = (r >= NN);
    size_t rp = (size_t)(bb ? (NP + (r - NN)) : r);
#pragma unroll
    for (int jp=0;jp<4;jp++){
      float2 v = up2(acc[i][jp]);
      int c0 = (tx<<3) + jp*2;
      if (c0 < Nn){
        float val = v.x + b1[c0];
        bf h,l; split_bf(val,h,l);
        Chi[rp*CC + c0] = h; Clo[rp*CC + c0] = l;
      }
      if (c0+1 < Nn){
        float val = v.y + b1[c0+1];
        bf h,l; split_bf(val,h,l);
        Chi[rp*CC + c0+1] = h; Clo[rp*CC + c0+1] = l;
      }
    }
  }
}

// ---------------- generic HMMA GEMM: out = act(A@W^T + b1 + b2) ----------------
// optional fused GroupNorm epilogue (gng != nullptr): requires gridDim.y == 1,
// relu=0; normalizes each row over 4 groups of 32 cols, writes Chi/Clo.
__global__ void __launch_bounds__(256,1)
k_hgemm(const bf* __restrict__ Ah, const bf* __restrict__ Al,
        const bf* __restrict__ Wh, const bf* __restrict__ Wl, int K,
        float* __restrict__ Cf, int ldc,
        bf* __restrict__ Chi, bf* __restrict__ Clo, int ldcb,
        const float* __restrict__ b1, const float* __restrict__ b2, int relu,
        const float* __restrict__ gng, const float* __restrict__ gnb)
{
  extern __shared__ __align__(16) char smem[];
  uint32_t sb = smem_u32(smem);
  int tid = threadIdx.x;
  int lane = tid & 31, wid = tid >> 5;
  int row0 = blockIdx.x * 128;
  int col0 = blockIdx.y * 128;

  int lr = tid >> 1, half = tid & 1;
  const bf* ah = Ah + (size_t)(row0 + lr)*K;
  const bf* al = Al + (size_t)(row0 + lr)*K;
  const bf* wh = Wh + (size_t)(col0 + lr)*K;
  const bf* wl = Wl + (size_t)(col0 + lr)*K;

  uint32_t doff[4];
#pragma unroll
  for (int j=0;j<4;j++){
    uint32_t c16 = half*4 + j;
    doff[j] = (uint32_t)lr*128u + ((c16 ^ ((uint32_t)lr & 7u)) * 16u);
  }

  int m_ = lane >> 3;
  int l7 = lane & 7;
  int wm = wid >> 1, wn = wid & 1;
  int arow = wm*32 + (m_&1)*8 + l7;
  int acb  = m_ >> 1;
  int bnp  = (m_>>1)*8 + l7;
  int bcb  = m_ & 1;

  float acc[2][8][4];
#pragma unroll
  for (int t=0;t<2;t++)
#pragma unroll
    for (int n=0;n<8;n++){ acc[t][n][0]=0.f; acc[t][n][1]=0.f; acc[t][n][2]=0.f; acc[t][n][3]=0.f; }

  int nch = K >> 6;
  {
    uint32_t base = sb;
#pragma unroll
    for (int j=0;j<4;j++){
      int moff = half*32 + j*8;
      cpa16(base + 0*TILE_B + doff[j], ah + moff, 16u);
      cpa16(base + 1*TILE_B + doff[j], al + moff, 16u);
      cpa16(base + 2*TILE_B + doff[j], wh + moff, 16u);
      cpa16(base + 3*TILE_B + doff[j], wl + moff, 16u);
    }
    CP_COMMIT();
  }

  for (int c=0; c<nch; c++){
    if (c + 1 < nch){
      uint32_t base = sb + (uint32_t)((c+1)&1)*BUF_B;
      int m0 = (c+1)*CHUNK + half*32;
#pragma unroll
      for (int j=0;j<4;j++){
        int moff = m0 + j*8;
        cpa16(base + 0*TILE_B + doff[j], ah + moff, 16u);
        cpa16(base + 1*TILE_B + doff[j], al + moff, 16u);
        cpa16(base + 2*TILE_B + doff[j], wh + moff, 16u);
        cpa16(base + 3*TILE_B + doff[j], wl + moff, 16u);
      }
      CP_COMMIT();
      CP_WAIT(1);
    } else {
      CP_WAIT(0);
    }
    __syncthreads();

    uint32_t bA = sb + (uint32_t)(c&1)*BUF_B;
#pragma unroll
    for (int ks=0; ks<4; ks++){
      uint32_t ahr[2][4], alr[2][4];
#pragma unroll
      for (int t=0;t<2;t++){
        uint32_t aoff = (uint32_t)(arow + t*16)*128u + ((((uint32_t)(ks*2 + acb)) ^ (uint32_t)l7) * 16u);
        ldsm4(bA + 0*TILE_B + aoff, ahr[t]);
        ldsm4(bA + 1*TILE_B + aoff, alr[t]);
      }
#pragma unroll
      for (int p=0;p<4;p++){
        uint32_t bhr[4], blr[4];
        uint32_t nB = (uint32_t)(wn*64 + p*16 + bnp);
        uint32_t boff = nB*128u + ((((uint32_t)(ks*2 + bcb)) ^ (uint32_t)l7) * 16u);
        ldsm4(bA + 2*TILE_B + boff, bhr);
        ldsm4(bA + 3*TILE_B + boff, blr);
#pragma unroll
        for (int t=0;t<2;t++){
          mma16816(acc[t][2*p+0], ahr[t], bhr[0], bhr[1]);
          mma16816(acc[t][2*p+0], ahr[t], blr[0], blr[1]);
          mma16816(acc[t][2*p+0], alr[t], bhr[0], bhr[1]);
          mma16816(acc[t][2*p+1], ahr[t], bhr[2], bhr[3]);
          mma16816(acc[t][2*p+1], ahr[t], blr[2], blr[3]);
          mma16816(acc[t][2*p+1], alr[t], bhr[2], bhr[3]);
        }
      }
    }
    __syncthreads();
  }

  if (gng){
    // ---- fused GroupNorm epilogue ----
    float* st = (float*)smem;   // [128][129]
#pragma unroll
    for (int t=0;t<2;t++){
      int rb = wm*32 + t*16 + (lane>>2);
#pragma unroll
      for (int n=0;n<8;n++){
        int cl = wn*64 + n*8 + (lane&3)*2;
        float bs0 = b1 ? b1[cl]   : 0.f;
        float bs1 = b1 ? b1[cl+1] : 0.f;
#pragma unroll
        for (int hrow=0;hrow<2;hrow++){
          int r = rb + hrow*8;
          st[r*129 + cl]     = acc[t][n][hrow*2+0] + bs0;
          st[r*129 + cl + 1] = acc[t][n][hrow*2+1] + bs1;
        }
      }
    }
    __syncthreads();
    int row = tid >> 1, hh = tid & 1;
#pragma unroll
    for (int g=0; g<2; g++){
      int cb = hh*64 + g*32;
      const float* sr = st + row*129 + cb;
      float mu = 0.f;
#pragma unroll
      for (int i=0;i<32;i++) mu += sr[i];
      mu *= (1.0f/32.0f);
      float var = 0.f;
#pragma unroll
      for (int i=0;i<32;i++){ float d = sr[i]-mu; var += d*d; }
      var *= (1.0f/32.0f);
      float inv = rsqrtf(var + 1e-5f);
      size_t ob0 = (size_t)(row0+row)*ldcb + cb;
#pragma unroll
      for (int i8=0; i8<4; i8++){
        uint32_t hp_[4], lp_[4];
#pragma unroll
        for (int q=0;q<4;q++){
          int i = i8*8 + q*2;
          float y0 = (sr[i]-mu)*inv*gng[cb+i]   + gnb[cb+i];
          float y1 = (sr[i+1]-mu)*inv*gng[cb+i+1] + gnb[cb+i+1];
          bf h0,l0,h1,l1;
          split_bf(y0,h0,l0); split_bf(y1,h1,l1);
          hp_[q] = ((uint32_t)__bfloat16_as_ushort(h1) << 16) | __bfloat16_as_ushort(h0);
          lp_[q] = ((uint32_t)__bfloat16_as_ushort(l1) << 16) | __bfloat16_as_ushort(l0);
        }
        *(uint4*)(Chi + ob0 + i8*8) = make_uint4(hp_[0],hp_[1],hp_[2],hp_[3]);
        *(uint4*)(Clo + ob0 + i8*8) = make_uint4(lp_[0],lp_[1],lp_[2],lp_[3]);
      }
    }
    return;
  }

#pragma unroll
  for (int t=0;t<2;t++){
    int rb = row0 + wm*32 + t*16 + (lane>>2);
#pragma unroll
    for (int n=0;n<8;n++){
      int cl = wn*64 + n*8 + (lane&3)*2;
      int cg = col0 + cl;
      float bsum0 = (b1 ? b1[cg]   : 0.f) + (b2 ? b2[cg]   : 0.f);
      float bsum1 = (b1 ? b1[cg+1] : 0.f) + (b2 ? b2[cg+1] : 0.f);
#pragma unroll
      for (int hrow=0;hrow<2;hrow++){
        int r = rb + hrow*8;
        float v0 = acc[t][n][hrow*2+0] + bsum0;
        float v1 = acc[t][n][hrow*2+1] + bsum1;
        if (relu){ v0 = fmaxf(v0, 0.f); v1 = fmaxf(v1, 0.f); }
        if (Cf){
          float2 vv; vv.x = v0; vv.y = v1;
          *(float2*)(Cf + (size_t)r*ldc + cg) = vv;
        }
        if (Chi){
          bf h0,l0,h1,l1;
          split_bf(v0,h0,l0); split_bf(v1,h1,l1);
          size_t o = (size_t)r*ldcb + cg;
          Chi[o] = h0; Chi[o+1] = h1;
          Clo[o] = l0; Clo[o+1] = l1;
        }
      }
    }
  }
}

// ---------------- adjacency HMMA ----------------
__global__ void __launch_bounds__(256,1)
k_hmma_diff(float* __restrict__ part)
{
  extern __shared__ __align__(16) char smem[];
  uint32_t sb = smem_u32(smem);
  int tid = threadIdx.x;
  int lane = tid & 31, wid = tid >> 5;
  int z = blockIdx.z;
  int b = z / RR, r = z - b*RR;
  int row0 = blockIdx.x * 128;

  int lr = tid >> 1, half = tid & 1;
  bool rowok = (row0 + lr) < NN;
  const bf* ah = g_adj_hi + ((size_t)z*NN + (rowok ? (row0+lr) : 0))*PADM;
  const bf* al = g_adj_lo + ((size_t)z*NN + (rowok ? (row0+lr) : 0))*PADM;
  const bf* bh = g_hwt_hi + ((size_t)((r*CC + lr)*2 + b))*PADM;
  const bf* bl = g_hwt_lo + ((size_t)((r*CC + lr)*2 + b))*PADM;
  uint32_t asz = rowok ? 16u : 0u;

  uint32_t doff[4];
#pragma unroll
  for (int j=0;j<4;j++){
    uint32_t c16 = half*4 + j;
    doff[j] = (uint32_t)lr*128u + ((c16 ^ ((uint32_t)lr & 7u)) * 16u);
  }

  int m_ = lane >> 3;
  int l7 = lane & 7;
  int wm = wid >> 1, wn = wid & 1;
  int arow = wm*32 + (m_&1)*8 + l7;
  int acb  = m_ >> 1;
  int bnp  = (m_>>1)*8 + l7;
  int bcb  = m_ & 1;

  float acc[2][8][4];
#pragma unroll
  for (int t=0;t<2;t++)
#pragma unroll
    for (int n=0;n<8;n++){ acc[t][n][0]=0.f; acc[t][n][1]=0.f; acc[t][n][2]=0.f; acc[t][n][3]=0.f; }

  {
    uint32_t base = sb;
#pragma unroll
    for (int j=0;j<4;j++){
      int moff = half*32 + j*8;
      cpa16(base + 0*TILE_B + doff[j], ah + moff, asz);
      cpa16(base + 1*TILE_B + doff[j], al + moff, asz);
      cpa16(base + 2*TILE_B + doff[j], bh + moff, 16u);
      cpa16(base + 3*TILE_B + doff[j], bl + moff, 16u);
    }
    CP_COMMIT();
  }

  for (int c=0; c<NCH; c++){
    if (c + 1 < NCH){
      uint32_t base = sb + (uint32_t)((c+1)&1)*BUF_B;
      int m0 = (c+1)*CHUNK + half*32;
#pragma unroll
      for (int j=0;j<4;j++){
        int moff = m0 + j*8;
        cpa16(base + 0*TILE_B + doff[j], ah + moff, asz);
        cpa16(base + 1*TILE_B + doff[j], al + moff, asz);
        cpa16(base + 2*TILE_B + doff[j], bh + moff, 16u);
        cpa16(base + 3*TILE_B + doff[j], bl + moff, 16u);
      }
      CP_COMMIT();
      CP_WAIT(1);
    } else {
      CP_WAIT(0);
    }
    __syncthreads();

    uint32_t bA = sb + (uint32_t)(c&1)*BUF_B;
#pragma unroll
    for (int ks=0; ks<4; ks++){
      uint32_t ahr[2][4], alr[2][4];
#pragma unroll
      for (int t=0;t<2;t++){
        uint32_t aoff = (uint32_t)(arow + t*16)*128u + ((((uint32_t)(ks*2 + acb)) ^ (uint32_t)l7) * 16u);
        ldsm4(bA + 0*TILE_B + aoff, ahr[t]);
        ldsm4(bA + 1*TILE_B + aoff, alr[t]);
      }
#pragma unroll
      for (int p=0;p<4;p++){
        uint32_t bhr[4], blr[4];
        uint32_t nB = (uint32_t)(wn*64 + p*16 + bnp);
        uint32_t boff = nB*128u + ((((uint32_t)(ks*2 + bcb)) ^ (uint32_t)l7) * 16u);
        ldsm4(bA + 2*TILE_B + boff, bhr);
        ldsm4(bA + 3*TILE_B + boff, blr);
#pragma unroll
        for (int t=0;t<2;t++){
          mma16816(acc[t][2*p+0], ahr[t], bhr[0], bhr[1]);
          mma16816(acc[t][2*p+0], ahr[t], blr[0], blr[1]);
          mma16816(acc[t][2*p+0], alr[t], bhr[0], bhr[1]);
          mma16816(acc[t][2*p+1], ahr[t], bhr[2], bhr[3]);
          mma16816(acc[t][2*p+1], ahr[t], blr[2], blr[3]);
          mma16816(acc[t][2*p+1], alr[t], bhr[2], bhr[3]);
        }
      }
    }
    __syncthreads();
  }

  float* pz = part + (size_t)z*NN*CC;
#pragma unroll
  for (int t=0;t<2;t++){
    int r0 = row0 + wm*32 + t*16 + (lane>>2);
#pragma unroll
    for (int n=0;n<8;n++){
      int c0 = wn*64 + n*8 + (lane&3)*2;
      if (r0 < NN){
        float2 v; v.x = acc[t][n][0]; v.y = acc[t][n][1];
        *(float2*)(pz + (size_t)r0*CC + c0) = v;
      }
      if (r0 + 8 < NN){
        float2 v; v.x = acc[t][n][2]; v.y = acc[t][n][3];
        *(float2*)(pz + (size_t)(r0+8)*CC + c0) = v;
      }
    }
  }
}

// ---------------- elementwise / conversion ----------------
__global__ void k_initzero(){
  int idx = blockIdx.x*256 + threadIdx.x;
  const int per = M3P*CC/8;
  if (idx >= 8*per) return;
  int a = idx / per, off = idx - a*per;
  float4* p;
  switch(a){
    case 0: p = (float4*)g_hdbh; break;
    case 1: p = (float4*)g_hdbl; break;
    case 2: p = (float4*)g_ovbh; break;
    case 3: p = (float4*)g_ovbl; break;
    case 4: p = (float4*)g_hrbh; break;
    case 5: p = (float4*)g_hrbl; break;
    case 6: p = (float4*)g_hbh;  break;
    default: p = (float4*)g_hbl; break;
  }
  p[off] = make_float4(0.f,0.f,0.f,0.f);
}

__global__ void k_cvtw(const float* __restrict__ qw, const float* __restrict__ kw,
                       const float* __restrict__ vw, const float* __restrict__ ow,
                       const float* __restrict__ w2, const float* __restrict__ ow1){
  int i = blockIdx.x*256 + threadIdx.x;
  if (i >= 16*QTR) return;
  float v; bf* dh; bf* dl; int di;
  if (i < 9*QTR){
    int l = i / (3*QTR);
    int rem = i - l*3*QTR;
    int which = rem / QTR;
    int within = rem - which*QTR;
    const float* src = (which==0) ? qw : (which==1) ? kw : vw;
    v = src[(size_t)l*QTR + within];
    dh = g_wqh; dl = g_wql; di = i;
  } else if (i < 12*QTR){
    int j = i - 9*QTR;
    v = ow[j];
    dh = g_woh; dl = g_wol; di = j;
  } else if (i < 15*QTR){
    int j = i - 12*QTR;
    int lc = j >> 7, k = j & 127;
    v = w2[(size_t)lc*(2*CC) + k];
    dh = g_w2h; dl = g_w2l; di = j;
  } else {
    int j = i - 15*QTR;
    v = ow1[j];
    dh = g_wo1h; dl = g_wo1l; di = j;
  }
  bf h, lo; split_bf(v, h, lo);
  dh[di] = h; dl[di] = lo;
}

__global__ void k_adjconv(const float* __restrict__ adj){
  int row = blockIdx.x;
  const float* src = adj + (size_t)row*NN;
  bf* dh = g_adj_hi + (size_t)row*PADM;
  bf* dl = g_adj_lo + (size_t)row*PADM;
#pragma unroll
  for (int t=0; t<PADM/256; t++){
    int m = threadIdx.x + t*256;
    float v = (m < NN) ? src[m] : 0.f;
    bf h,l; split_bf(v,h,l);
    dh[m] = h; dl[m] = l;
  }
}

// all layers' wms (hi/lo) in one shot
__global__ void k_wmsball(const float* __restrict__ tr, const float* __restrict__ cw)
{
  int idx = blockIdx.x*256 + threadIdx.x;
  if (idx >= LL*RR*CC*CC) return;
  int l = idx / (RR*CC*CC);
  int rem = idx - l*RR*CC*CC;
  int r = rem >> 14;
  int oc = rem & 16383;
  const float* base = tr + (((size_t)(l*RR + r)*KKc) << 14) + oc;
  float s = 0.f;
#pragma unroll
  for (int k=0;k<KKc;k++) s += base[(size_t)k << 14];
  float v = cw[l*RR + r] * s * (1.0f/KKc);
  bf h,lo; split_bf(v,h,lo);
  g_wmsh[idx] = h; g_wmsl[idx] = lo;
}

// h_prime recurrence + all-layer qkv bias gather (weights-only)
__global__ void __launch_bounds__(1024,1)
k_hpvec(const float* __restrict__ w1, const float* __restrict__ b1,
        const float* __restrict__ eb1, const float* __restrict__ w2,
        const float* __restrict__ b2, const float* __restrict__ eb2,
        const float* __restrict__ qb, const float* __restrict__ kb,
        const float* __restrict__ vb)
{
  extern __shared__ float sw[];
  float* s1 = sw;                    // [CC][HPV_PITCH]
  float* s2 = sw + CC*HPV_PITCH;     // [CC][HPV_PITCH]
  float* hp = sw + 2*CC*HPV_PITCH;   // [CC]
  int tid = threadIdx.x;
  // qkv biases, all layers
  for (int i = tid; i < LL*3*CC; i += 1024){
    int l = i / (3*CC);
    int rem = i - l*3*CC;
    int which = rem >> 7, c = rem & 127;
    const float* s = (which==0) ? qb : (which==1) ? kb : vb;
    g_bqkv[i] = s[l*CC + c];
  }
  if (tid < CC) hp[tid] = 0.f;
  int c = tid >> 3, g = tid & 7;
  for (int l=0; l<LL; l++){
    __syncthreads();
    for (int j = tid; j < CC*CC/2; j += 1024){
      int cc = j >> 6;
      int k2 = (j & 63) << 1;
      float2 v1 = *(const float2*)(w1 + (size_t)l*QTR + cc*CC + k2);
      float2 v2 = *(const float2*)(w2 + ((size_t)(l*CC)+cc)*(2*CC) + CC + k2);
      *(float2*)(s1 + cc*HPV_PITCH + k2) = v1;
      *(float2*)(s2 + cc*HPV_PITCH + k2) = v2;
    }
    __syncthreads();
    float nh = 0.f, bv = 0.f;
#pragma unroll
    for (int kk=0; kk<16; kk++){
      int k = kk*8 + g;
      float hv = hp[k];
      nh += hv * s1[c*HPV_PITCH + k];
      bv += hv * s2[c*HPV_PITCH + k];
    }
#pragma unroll
    for (int o=4;o>0;o>>=1){
      nh += __shfl_xor_sync(0xffffffffu, nh, o);
      bv += __shfl_xor_sync(0xffffffffu, bv, o);
    }
    __syncthreads();
    if (g == 0){
      g_bv[l*CC+c] = bv + b2[l*CC+c] + eb2[l*CC+c];
      hp[c] = fmaxf(nh + b1[l*CC+c] + eb1[l*CC+c], 0.f);
    }
  }
}

__global__ void k_reduce(const float* __restrict__ convb, int l)
{
  int idx = blockIdx.x*256 + threadIdx.x;
  if (idx >= M3*CC) return;
  int b = idx / (NN*CC);
  int in = idx - b*NN*CC;
  int n = in / CC, c = in - n*CC;
  const float* p = g_part + (size_t)b*RR*NN*CC + in;
  float s = convb[l];
#pragma unroll
  for (int j=0;j<RR;j++) s += p[(size_t)j*NN*CC];
  s = fmaxf(s, 0.f);
  bf h,lo; split_bf(s,h,lo);
  size_t o = (size_t)(b*NP + n)*CC + c;
  g_hdbh[o] = h; g_hdbl[o] = lo;
}

__global__ void k_ret()
{
  int m = blockIdx.x, c = threadIdx.x;
  int b = m / NN;
  size_t mp = (size_t)(b*NP + (m - b*NN));
  const float* bp = g_qkv + mp*384;
  float q = bp[c], kk = bp[128+c], v = bp[256+c];
  float s = q*kk;
#pragma unroll
  for (int o=16;o>0;o>>=1) s += __shfl_xor_sync(0xffffffffu, s, o);
  float ov = s*v;
  bf h,lo; split_bf(ov,h,lo);
  g_ovbh[mp*128 + c] = h; g_ovbl[mp*128 + c] = lo;
}

__global__ void k_out2(const float* __restrict__ w, const float* __restrict__ bb,
                       float* __restrict__ out)
{
  int row = blockIdx.x, c = threadIdx.x;
  int b = row / NN;
  size_t mp = (size_t)(b*NP + (row - b*NN));
  float x = g_hmid[mp*128 + c];
  float s0 = x * w[c];
  float s1 = x * w[128 + c];
#pragma unroll
  for (int o=16;o>0;o>>=1){
    s0 += __shfl_xor_sync(0xffffffffu, s0, o);
    s1 += __shfl_xor_sync(0xffffffffu, s1, o);
  }
  __shared__ float sm[2][4];
  int wid = c >> 5;
  if ((c & 31) == 0){ sm[0][wid] = s0; sm[1][wid] = s1; }
  __syncthreads();
  if (c == 0) out[row*2 + 0] = sm[0][0]+sm[0][1]+sm[0][2]+sm[0][3] + bb[0];
  if (c == 1) out[row*2 + 1] = sm[1][0]+sm[1][1]+sm[1][2]+sm[1][3] + bb[1];
}

// ---------------- host ----------------
extern "C" void kernel_launch(void* const* d_in, const int* in_sizes, int n_in,
                              void* d_out, int out_size)
{
  (void)in_sizes; (void)n_in; (void)out_size;
  const float* x     = (const float*)d_in[0];
  const float* adj   = (const float*)d_in[1];
  const float* emb_w = (const float*)d_in[2];
  const float* emb_b = (const float*)d_in[3];
  const float* tr    = (const float*)d_in[5];
  const float* cw    = (const float*)d_in[6];
  const float* cb    = (const float*)d_in[7];
  const float* qw    = (const float*)d_in[8];
  const float* qb    = (const float*)d_in[9];
  const float* kw    = (const float*)d_in[10];
  const float* kb    = (const float*)d_in[11];
  const float* vw    = (const float*)d_in[12];
  const float* vb    = (const float*)d_in[13];
  const float* ow    = (const float*)d_in[14];
  const float* ob    = (const float*)d_in[15];
  const float* gg    = (const float*)d_in[16];
  const float* gb    = (const float*)d_in[17];
  const float* w1    = (const float*)d_in[18];
  const float* b1    = (const float*)d_in[19];
  const float* eb1   = (const float*)d_in[20];
  const float* w2    = (const float*)d_in[21];
  const float* b2    = (const float*)d_in[22];
  const float* eb2   = (const float*)d_in[23];
  const float* ow1   = (const float*)d_in[24];
  const float* ob1   = (const float*)d_in[25];
  const float* ow2   = (const float*)d_in[26];
  const float* ob2   = (const float*)d_in[27];
  float* out = (float*)d_out;

  float *p_part, *p_qkv, *p_hmid, *p_bqkv, *p_bv;
  bf *p_hbh,*p_hbl,*p_hdbh,*p_hdbl,*p_ovbh,*p_ovbl,*p_hrbh,*p_hrbl;
  bf *p_wqh,*p_wql,*p_woh,*p_wol,*p_w2h,*p_w2l,*p_wo1h,*p_wo1l,*p_wmsh,*p_wmsl;
  bf *p_hwth,*p_hwtl;
  cudaGetSymbolAddress((void**)&p_part, g_part);
  cudaGetSymbolAddress((void**)&p_qkv,  g_qkv);
  cudaGetSymbolAddress((void**)&p_hmid, g_hmid);
  cudaGetSymbolAddress((void**)&p_bqkv, g_bqkv);
  cudaGetSymbolAddress((void**)&p_bv,   g_bv);
  cudaGetSymbolAddress((void**)&p_hbh,  g_hbh);  cudaGetSymbolAddress((void**)&p_hbl,  g_hbl);
  cudaGetSymbolAddress((void**)&p_hdbh, g_hdbh); cudaGetSymbolAddress((void**)&p_hdbl, g_hdbl);
  cudaGetSymbolAddress((void**)&p_ovbh, g_ovbh); cudaGetSymbolAddress((void**)&p_ovbl, g_ovbl);
  cudaGetSymbolAddress((void**)&p_hrbh, g_hrbh); cudaGetSymbolAddress((void**)&p_hrbl, g_hrbl);
  cudaGetSymbolAddress((void**)&p_wqh,  g_wqh);  cudaGetSymbolAddress((void**)&p_wql,  g_wql);
  cudaGetSymbolAddress((void**)&p_woh,  g_woh);  cudaGetSymbolAddress((void**)&p_wol,  g_wol);
  cudaGetSymbolAddress((void**)&p_w2h,  g_w2h);  cudaGetSymbolAddress((void**)&p_w2l,  g_w2l);
  cudaGetSymbolAddress((void**)&p_wo1h, g_wo1h); cudaGetSymbolAddress((void**)&p_wo1l, g_wo1l);
  cudaGetSymbolAddress((void**)&p_wmsh, g_wmsh); cudaGetSymbolAddress((void**)&p_wmsl, g_wmsl);
  cudaGetSymbolAddress((void**)&p_hwth, g_hwt_hi); cudaGetSymbolAddress((void**)&p_hwtl, g_hwt_lo);

  cudaFuncSetAttribute(k_hmma_diff, cudaFuncAttributeMaxDynamicSharedMemorySize, SMEM_HMMA);
  cudaFuncSetAttribute(k_hgemm,     cudaFuncAttributeMaxDynamicSharedMemorySize, SMEM_HMMA);
  cudaFuncSetAttribute(k_hpvec,     cudaFuncAttributeMaxDynamicSharedMemorySize, SMEM_HPV);

  dim3 blk(256);
  const int GRT = M3P/128;  // 24

  // (1) embed: fp32 FFMA GEMM with fused bf16 hi/lo padded epilogue
  k_gemm<<<dim3((M3+63)/64,1,1), blk>>>(x + (TT-1)*DINc, TT*DINc, emb_w, DINc,
                                        p_hbh, p_hbl, M3, CC, DINc, emb_b);
  // (2) all layers' wms
  k_wmsball<<<(LL*RR*CC*CC + 255)/256, 256>>>(tr, cw);
  // (3) adjacency split
  k_adjconv<<<NB*RR*NN, 256>>>(adj);

  for (int l = 0; l < LL; l++){
    // (4 on l=0 -> PROFILED) hwt[(o*2+b)][m'] = wms_l @ h^T, bf hi/lo epilogue
    k_hgemm<<<dim3(RR, GRT, 1), blk, SMEM_HMMA>>>(p_wmsh + (size_t)l*RR*QTR, p_wmsl + (size_t)l*RR*QTR,
                                                  p_hbh, p_hbl, CC,
                                                  nullptr, 0, p_hwth, p_hwtl, M3P,
                                                  nullptr, nullptr, 0, nullptr, nullptr);
    k_hmma_diff<<<dim3(NROWT,1,NB*RR), blk, SMEM_HMMA>>>(p_part);
    k_reduce<<<(M3*CC + 255)/256, 256>>>(cb, l);

    if (l == 0){
      k_cvtw<<<(16*QTR + 255)/256, 256>>>(qw, kw, vw, ow, w2, ow1);
      k_hpvec<<<1, 1024, SMEM_HPV>>>(w1, b1, eb1, w2, b2, eb2, qb, kb, vb);
    }

    k_hgemm<<<dim3(GRT,3,1), blk, SMEM_HMMA>>>(p_hdbh, p_hdbl,
                                               p_wqh + (size_t)l*3*QTR, p_wql + (size_t)l*3*QTR, CC,
                                               p_qkv, 3*CC, nullptr, nullptr, 0,
                                               p_bqkv + l*3*CC, nullptr, 0, nullptr, nullptr);
    k_ret<<<M3, 128>>>();
    // obf = ov @ ow^T + ob, fused GroupNorm -> hrb
    k_hgemm<<<dim3(GRT,1,1), blk, SMEM_HMMA>>>(p_ovbh, p_ovbl,
                                               p_woh + (size_t)l*QTR, p_wol + (size_t)l*QTR, CC,
                                               nullptr, 0, p_hrbh, p_hrbl, CC,
                                               ob + l*CC, nullptr, 0,
                                               gg + l*CC, gb + l*CC);
    // h = relu(hr @ w2[:, :128]^T + bv_l)
    k_hgemm<<<dim3(GRT,1,1), blk, SMEM_HMMA>>>(p_hrbh, p_hrbl,
                                               p_w2h + (size_t)l*QTR, p_w2l + (size_t)l*QTR, CC,
                                               nullptr, 0, p_hbh, p_hbl, CC,
                                               p_bv + l*CC, nullptr, 1, nullptr, nullptr);
  }

  k_hgemm<<<dim3(GRT,1,1), blk, SMEM_HMMA>>>(p_hbh, p_hbl, p_wo1h, p_wo1l, CC,
                                             p_hmid, CC, nullptr, nullptr, 0,
                                             ob1, nullptr, 1, nullptr, nullptr);
  k_out2<<<M3, 128>>>(ow2, ob2, out);
  // restore zero-padding invariant for the next replay (module-load zeros cover run 1)
  k_initzero<<<(8*(M3P*CC/8) + 255)/256, 256>>>();
}

// round 12
// speedup vs baseline: 1.1273x; 1.1106x over previous
#include <cuda_runtime.h>
#include <cuda_bf16.h>
#include <cstdint>

typedef unsigned long long ull;
typedef __nv_bfloat16 bf;

#define NB 2
#define NN 1500
#define TT 20
#define DINc 32
#define CC 128
#define RR 5
#define KKc 5
#define LL 3
#define M3 (NB*NN)
#define NP 1536
#define M3P (NB*NP)
#define PADM 1536
#define NROWT 12
#define CHUNK 64
#define NCH (PADM/CHUNK)
#define TILE_B 16384
#define BUF_B (4*TILE_B)
#define SMEM_HMMA (2*BUF_B)
#define HPV_PITCH 136
#define SMEM_HPV ((2*CC*HPV_PITCH + CC)*4)
#define QTR (CC*CC)

// ---------------- scratch ----------------
__device__ bf g_hbh[M3P*CC], g_hbl[M3P*CC];
__device__ bf g_wmsh[LL*RR*CC*CC], g_wmsl[LL*RR*CC*CC];
__device__ float g_bqkv[LL*3*CC];
__device__ float g_bv[LL*CC];
__device__ bf g_adj_hi[NB*RR*NN*PADM];
__device__ bf g_adj_lo[NB*RR*NN*PADM];
__device__ bf g_hwt_hi[RR*CC*NB*PADM];
__device__ bf g_hwt_lo[RR*CC*NB*PADM];
__device__ float g_part[NB*RR*NN*CC];
__device__ bf g_hdbh[M3P*CC], g_hdbl[M3P*CC];
__device__ float g_qkv[M3P*3*CC];
__device__ bf g_ovbh[M3P*CC], g_ovbl[M3P*CC];
__device__ bf g_hrbh[M3P*CC], g_hrbl[M3P*CC];
__device__ float g_hmid[M3P*CC];
// weight slabs (hi/lo)
__device__ bf g_wqh[LL*3*CC*CC], g_wql[LL*3*CC*CC];
__device__ bf g_woh[LL*CC*CC],   g_wol[LL*CC*CC];
__device__ bf g_w2h[LL*CC*CC],   g_w2l[LL*CC*CC];
__device__ bf g_wo1h[CC*CC],     g_wo1l[CC*CC];

// ---------------- helpers ----------------
__device__ __forceinline__ ull pk2(float x, float y){
  ull r; asm("mov.b64 %0,{%1,%2};" : "=l"(r) : "f"(x), "f"(y)); return r;
}
__device__ __forceinline__ void fma2(ull &c, ull a, ull b){
  asm("fma.rn.f32x2 %0, %1, %2, %0;" : "+l"(c) : "l"(a), "l"(b));
}
__device__ __forceinline__ float2 up2(ull a){
  float2 v; asm("mov.b64 {%0,%1}, %2;" : "=f"(v.x), "=f"(v.y) : "l"(a)); return v;
}
__device__ __forceinline__ float4 ld4(const float* __restrict__ p, int k, int Ke){
  float4 v = make_float4(0.f,0.f,0.f,0.f);
  if (k + 4 <= Ke) v = *(const float4*)(p + k);
  else {
    if (k   < Ke) v.x = p[k];
    if (k+1 < Ke) v.y = p[k+1];
    if (k+2 < Ke) v.z = p[k+2];
    if (k+3 < Ke) v.w = p[k+3];
  }
  return v;
}
__device__ __forceinline__ uint32_t smem_u32(const void* p){
  uint32_t a; asm("{ .reg .u64 t; cvta.to.shared.u64 t, %1; cvt.u32.u64 %0, t; }" : "=r"(a) : "l"(p));
  return a;
}
__device__ __forceinline__ void cpa16(uint32_t d, const void* s, uint32_t sz){
  asm volatile("cp.async.cg.shared.global [%0], [%1], 16, %2;" :: "r"(d), "l"(s), "r"(sz) : "memory");
}
#define CP_COMMIT() asm volatile("cp.async.commit_group;" ::: "memory")
#define CP_WAIT(n)  asm volatile("cp.async.wait_group %0;" :: "n"(n) : "memory")
__device__ __forceinline__ void ldsm4(uint32_t a, uint32_t* r){
  asm volatile("ldmatrix.sync.aligned.m8n8.x4.shared.b16 {%0,%1,%2,%3}, [%4];"
    : "=r"(r[0]), "=r"(r[1]), "=r"(r[2]), "=r"(r[3]) : "r"(a));
}
__device__ __forceinline__ void mma16816(float* c, const uint32_t* a, uint32_t b0, uint32_t b1){
  asm volatile("mma.sync.aligned.m16n8k16.row.col.f32.bf16.bf16.f32 "
    "{%0,%1,%2,%3},{%4,%5,%6,%7},{%8,%9},{%0,%1,%2,%3};"
    : "+f"(c[0]), "+f"(c[1]), "+f"(c[2]), "+f"(c[3])
    : "r"(a[0]), "r"(a[1]), "r"(a[2]), "r"(a[3]), "r"(b0), "r"(b1));
}
__device__ __forceinline__ void split_bf(float v, bf& h, bf& l){
  h = __float2bfloat16(v);
  l = __float2bfloat16(v - __bfloat162float(h));
}

// ---------------- FFMA GEMM (embed only): writes padded bf hi/lo ----------------
#define PA 65
#define PB 132
__global__ void __launch_bounds__(256,2)
k_gemm(const float* __restrict__ A, int lda,
       const float* __restrict__ Bw, int ldb,
       bf* __restrict__ Chi, bf* __restrict__ Clo,
       int M, int Nn, int K,
       const float* __restrict__ b1)
{
  __shared__ float As[16*PA];
  __shared__ float Bs[16*PB];
  int row0 = blockIdx.x*64, col0 = 0;
  int tid = threadIdx.x;
  int arow = tid >> 2;
  int akq  = (tid & 3) << 2;
  bool aok = (row0 + arow) < M;
  const float* Arow = A + (size_t)(aok ? (row0+arow) : 0)*lda;
  int bn  = tid >> 2;
  int bkq = (tid & 3) << 2;
  int ty = tid >> 4, tx = tid & 15;

  ull acc[4][4];
#pragma unroll
  for (int i=0;i<4;i++){ acc[i][0]=0ULL; acc[i][1]=0ULL; acc[i][2]=0ULL; acc[i][3]=0ULL; }

  int nT = (K + 15) >> 4;
  for (int t=0; t<nT; t++){
    int k0 = t << 4;
    int Ke = K - k0;
    float4 av = aok ? ld4(Arow + k0, akq, Ke) : make_float4(0,0,0,0);
    As[(akq+0)*PA + arow] = av.x;
    As[(akq+1)*PA + arow] = av.y;
    As[(akq+2)*PA + arow] = av.z;
    As[(akq+3)*PA + arow] = av.w;
#pragma unroll
    for (int hh=0; hh<2; hh++){
      int n = bn + hh*64;
      int col = col0 + n;
      float4 bv = (col < Nn) ? ld4(Bw + (size_t)col*ldb + k0, bkq, Ke)
                             : make_float4(0,0,0,0);
      Bs[(bkq+0)*PB + n] = bv.x;
      Bs[(bkq+1)*PB + n] = bv.y;
      Bs[(bkq+2)*PB + n] = bv.z;
      Bs[(bkq+3)*PB + n] = bv.w;
    }
    __syncthreads();
#pragma unroll
    for (int k=0;k<16;k++){
      const float* ap = &As[k*PA + (ty<<2)];
      float a0=ap[0], a1=ap[1], a2=ap[2], a3=ap[3];
      const float4* bp4 = (const float4*)&Bs[k*PB + (tx<<3)];
      float4 b0v = bp4[0], b1v = bp4[1];
      ull p0=pk2(b0v.x,b0v.y), p1=pk2(b0v.z,b0v.w);
      ull p2=pk2(b1v.x,b1v.y), p3=pk2(b1v.z,b1v.w);
      ull ad;
      ad=pk2(a0,a0); fma2(acc[0][0],ad,p0); fma2(acc[0][1],ad,p1); fma2(acc[0][2],ad,p2); fma2(acc[0][3],ad,p3);
      ad=pk2(a1,a1); fma2(acc[1][0],ad,p0); fma2(acc[1][1],ad,p1); fma2(acc[1][2],ad,p2); fma2(acc[1][3],ad,p3);
      ad=pk2(a2,a2); fma2(acc[2][0],ad,p0); fma2(acc[2][1],ad,p1); fma2(acc[2][2],ad,p2); fma2(acc[2][3],ad,p3);
      ad=pk2(a3,a3); fma2(acc[3][0],ad,p0); fma2(acc[3][1],ad,p1); fma2(acc[3][2],ad,p2); fma2(acc[3][3],ad,p3);
    }
    __syncthreads();
  }
#pragma unroll
  for (int i=0;i<4;i++){
    int r = row0 + (ty<<2) + i;
    if (r >= M) continue;
    int bb = (r >= NN);
    size_t rp = (size_t)(bb ? (NP + (r - NN)) : r);
#pragma unroll
    for (int jp=0;jp<4;jp++){
      float2 v = up2(acc[i][jp]);
      int c0 = (tx<<3) + jp*2;
      if (c0 < Nn){
        float val = v.x + b1[c0];
        bf h,l; split_bf(val,h,l);
        Chi[rp*CC + c0] = h; Clo[rp*CC + c0] = l;
      }
      if (c0+1 < Nn){
        float val = v.y + b1[c0+1];
        bf h,l; split_bf(val,h,l);
        Chi[rp*CC + c0+1] = h; Clo[rp*CC + c0+1] = l;
      }
    }
  }
}

// ---------------- generic HMMA GEMM, 512 threads (16 warps, 4x4, 32x32/warp) ----
// out = act(A@W^T + b1 + b2); optional fused GroupNorm epilogue (gng != nullptr,
// requires gridDim.y==1, relu=0).
__global__ void __launch_bounds__(512,1)
k_hgemm(const bf* __restrict__ Ah, const bf* __restrict__ Al,
        const bf* __restrict__ Wh, const bf* __restrict__ Wl, int K,
        float* __restrict__ Cf, int ldc,
        bf* __restrict__ Chi, bf* __restrict__ Clo, int ldcb,
        const float* __restrict__ b1, const float* __restrict__ b2, int relu,
        const float* __restrict__ gng, const float* __restrict__ gnb)
{
  extern __shared__ __align__(16) char smem[];
  uint32_t sb = smem_u32(smem);
  int tid = threadIdx.x;
  int lane = tid & 31, wid = tid >> 5;
  int row0 = blockIdx.x * 128;
  int col0 = blockIdx.y * 128;

  int lr = tid >> 2, q = tid & 3;
  const bf* ah = Ah + (size_t)(row0 + lr)*K;
  const bf* al = Al + (size_t)(row0 + lr)*K;
  const bf* wh = Wh + (size_t)(col0 + lr)*K;
  const bf* wl = Wl + (size_t)(col0 + lr)*K;

  uint32_t doff[2];
#pragma unroll
  for (int j=0;j<2;j++){
    uint32_t c16 = q*2 + j;
    doff[j] = (uint32_t)lr*128u + ((c16 ^ ((uint32_t)lr & 7u)) * 16u);
  }

  int m_ = lane >> 3;
  int l7 = lane & 7;
  int wm = wid >> 2, wn = wid & 3;
  int arow = wm*32 + (m_&1)*8 + l7;
  int acb  = m_ >> 1;
  int bnp  = (m_>>1)*8 + l7;
  int bcb  = m_ & 1;

  float acc[2][4][4];
#pragma unroll
  for (int t=0;t<2;t++)
#pragma unroll
    for (int n=0;n<4;n++){ acc[t][n][0]=0.f; acc[t][n][1]=0.f; acc[t][n][2]=0.f; acc[t][n][3]=0.f; }

  int nch = K >> 6;
  {
    uint32_t base = sb;
#pragma unroll
    for (int j=0;j<2;j++){
      int moff = q*16 + j*8;
      cpa16(base + 0*TILE_B + doff[j], ah + moff, 16u);
      cpa16(base + 1*TILE_B + doff[j], al + moff, 16u);
      cpa16(base + 2*TILE_B + doff[j], wh + moff, 16u);
      cpa16(base + 3*TILE_B + doff[j], wl + moff, 16u);
    }
    CP_COMMIT();
  }

  for (int c=0; c<nch; c++){
    if (c + 1 < nch){
      uint32_t base = sb + (uint32_t)((c+1)&1)*BUF_B;
      int m0 = (c+1)*CHUNK + q*16;
#pragma unroll
      for (int j=0;j<2;j++){
        int moff = m0 + j*8;
        cpa16(base + 0*TILE_B + doff[j], ah + moff, 16u);
        cpa16(base + 1*TILE_B + doff[j], al + moff, 16u);
        cpa16(base + 2*TILE_B + doff[j], wh + moff, 16u);
        cpa16(base + 3*TILE_B + doff[j], wl + moff, 16u);
      }
      CP_COMMIT();
      CP_WAIT(1);
    } else {
      CP_WAIT(0);
    }
    __syncthreads();

    uint32_t bA = sb + (uint32_t)(c&1)*BUF_B;
#pragma unroll
    for (int ks=0; ks<4; ks++){
      uint32_t ahr[2][4], alr[2][4];
#pragma unroll
      for (int t=0;t<2;t++){
        uint32_t aoff = (uint32_t)(arow + t*16)*128u + ((((uint32_t)(ks*2 + acb)) ^ (uint32_t)l7) * 16u);
        ldsm4(bA + 0*TILE_B + aoff, ahr[t]);
        ldsm4(bA + 1*TILE_B + aoff, alr[t]);
      }
#pragma unroll
      for (int p=0;p<2;p++){
        uint32_t bhr[4], blr[4];
        uint32_t nB = (uint32_t)(wn*32 + p*16 + bnp);
        uint32_t boff = nB*128u + ((((uint32_t)(ks*2 + bcb)) ^ (uint32_t)l7) * 16u);
        ldsm4(bA + 2*TILE_B + boff, bhr);
        ldsm4(bA + 3*TILE_B + boff, blr);
#pragma unroll
        for (int t=0;t<2;t++){
          mma16816(acc[t][2*p+0], ahr[t], bhr[0], bhr[1]);
          mma16816(acc[t][2*p+0], ahr[t], blr[0], blr[1]);
          mma16816(acc[t][2*p+0], alr[t], bhr[0], bhr[1]);
          mma16816(acc[t][2*p+1], ahr[t], bhr[2], bhr[3]);
          mma16816(acc[t][2*p+1], ahr[t], blr[2], blr[3]);
          mma16816(acc[t][2*p+1], alr[t], bhr[2], bhr[3]);
        }
      }
    }
    __syncthreads();
  }

  if (gng){
    // ---- fused GroupNorm epilogue (512 thr = 128 rows x 4 groups) ----
    float* st = (float*)smem;   // [128][129]
#pragma unroll
    for (int t=0;t<2;t++){
      int rb = wm*32 + t*16 + (lane>>2);
#pragma unroll
      for (int n=0;n<4;n++){
        int cl = wn*32 + (n>>1)*16 + (n&1)*8 + (lane&3)*2;
        float bs0 = b1 ? b1[cl]   : 0.f;
        float bs1 = b1 ? b1[cl+1] : 0.f;
#pragma unroll
        for (int hrow=0;hrow<2;hrow++){
          int r = rb + hrow*8;
          st[r*129 + cl]     = acc[t][n][hrow*2+0] + bs0;
          st[r*129 + cl + 1] = acc[t][n][hrow*2+1] + bs1;
        }
      }
    }
    __syncthreads();
    int row = tid >> 2, g = tid & 3;
    int cb = g*32;
    const float* sr = st + row*129 + cb;
    float mu = 0.f;
#pragma unroll
    for (int i=0;i<32;i++) mu += sr[i];
    mu *= (1.0f/32.0f);
    float var = 0.f;
#pragma unroll
    for (int i=0;i<32;i++){ float d = sr[i]-mu; var += d*d; }
    var *= (1.0f/32.0f);
    float inv = rsqrtf(var + 1e-5f);
    size_t ob0 = (size_t)(row0+row)*ldcb + cb;
#pragma unroll
    for (int i8=0; i8<4; i8++){
      uint32_t hp_[4], lp_[4];
#pragma unroll
      for (int qq=0;qq<4;qq++){
        int i = i8*8 + qq*2;
        float y0 = (sr[i]-mu)*inv*gng[cb+i]   + gnb[cb+i];
        float y1 = (sr[i+1]-mu)*inv*gng[cb+i+1] + gnb[cb+i+1];
        bf h0,l0,h1,l1;
        split_bf(y0,h0,l0); split_bf(y1,h1,l1);
        hp_[qq] = ((uint32_t)__bfloat16_as_ushort(h1) << 16) | __bfloat16_as_ushort(h0);
        lp_[qq] = ((uint32_t)__bfloat16_as_ushort(l1) << 16) | __bfloat16_as_ushort(l0);
      }
      *(uint4*)(Chi + ob0 + i8*8) = make_uint4(hp_[0],hp_[1],hp_[2],hp_[3]);
      *(uint4*)(Clo + ob0 + i8*8) = make_uint4(lp_[0],lp_[1],lp_[2],lp_[3]);
    }
    return;
  }

#pragma unroll
  for (int t=0;t<2;t++){
    int rb = row0 + wm*32 + t*16 + (lane>>2);
#pragma unroll
    for (int n=0;n<4;n++){
      int cl = wn*32 + (n>>1)*16 + (n&1)*8 + (lane&3)*2;
      int cg = col0 + cl;
      float bsum0 = (b1 ? b1[cg]   : 0.f) + (b2 ? b2[cg]   : 0.f);
      float bsum1 = (b1 ? b1[cg+1] : 0.f) + (b2 ? b2[cg+1] : 0.f);
#pragma unroll
      for (int hrow=0;hrow<2;hrow++){
        int r = rb + hrow*8;
        float v0 = acc[t][n][hrow*2+0] + bsum0;
        float v1 = acc[t][n][hrow*2+1] + bsum1;
        if (relu){ v0 = fmaxf(v0, 0.f); v1 = fmaxf(v1, 0.f); }
        if (Cf){
          float2 vv; vv.x = v0; vv.y = v1;
          *(float2*)(Cf + (size_t)r*ldc + cg) = vv;
        }
        if (Chi){
          bf h0,l0,h1,l1;
          split_bf(v0,h0,l0); split_bf(v1,h1,l1);
          size_t o = (size_t)r*ldcb + cg;
          Chi[o] = h0; Chi[o+1] = h1;
          Clo[o] = l0; Clo[o+1] = l1;
        }
      }
    }
  }
}

// ---------------- adjacency HMMA, 512 threads ----------------
__global__ void __launch_bounds__(512,1)
k_hmma_diff(float* __restrict__ part)
{
  extern __shared__ __align__(16) char smem[];
  uint32_t sb = smem_u32(smem);
  int tid = threadIdx.x;
  int lane = tid & 31, wid = tid >> 5;
  int z = blockIdx.z;
  int b = z / RR, r = z - b*RR;
  int row0 = blockIdx.x * 128;

  int lr = tid >> 2, q = tid & 3;
  bool rowok = (row0 + lr) < NN;
  const bf* ah = g_adj_hi + ((size_t)z*NN + (rowok ? (row0+lr) : 0))*PADM;
  const bf* al = g_adj_lo + ((size_t)z*NN + (rowok ? (row0+lr) : 0))*PADM;
  const bf* bh = g_hwt_hi + ((size_t)((r*CC + lr)*2 + b))*PADM;
  const bf* bl = g_hwt_lo + ((size_t)((r*CC + lr)*2 + b))*PADM;
  uint32_t asz = rowok ? 16u : 0u;

  uint32_t doff[2];
#pragma unroll
  for (int j=0;j<2;j++){
    uint32_t c16 = q*2 + j;
    doff[j] = (uint32_t)lr*128u + ((c16 ^ ((uint32_t)lr & 7u)) * 16u);
  }

  int m_ = lane >> 3;
  int l7 = lane & 7;
  int wm = wid >> 2, wn = wid & 3;
  int arow = wm*32 + (m_&1)*8 + l7;
  int acb  = m_ >> 1;
  int bnp  = (m_>>1)*8 + l7;
  int bcb  = m_ & 1;

  float acc[2][4][4];
#pragma unroll
  for (int t=0;t<2;t++)
#pragma unroll
    for (int n=0;n<4;n++){ acc[t][n][0]=0.f; acc[t][n][1]=0.f; acc[t][n][2]=0.f; acc[t][n][3]=0.f; }

  {
    uint32_t base = sb;
#pragma unroll
    for (int j=0;j<2;j++){
      int moff = q*16 + j*8;
      cpa16(base + 0*TILE_B + doff[j], ah + moff, asz);
      cpa16(base + 1*TILE_B + doff[j], al + moff, asz);
      cpa16(base + 2*TILE_B + doff[j], bh + moff, 16u);
      cpa16(base + 3*TILE_B + doff[j], bl + moff, 16u);
    }
    CP_COMMIT();
  }

  for (int c=0; c<NCH; c++){
    if (c + 1 < NCH){
      uint32_t base = sb + (uint32_t)((c+1)&1)*BUF_B;
      int m0 = (c+1)*CHUNK + q*16;
#pragma unroll
      for (int j=0;j<2;j++){
        int moff = m0 + j*8;
        cpa16(base + 0*TILE_B + doff[j], ah + moff, asz);
        cpa16(base + 1*TILE_B + doff[j], al + moff, asz);
        cpa16(base + 2*TILE_B + doff[j], bh + moff, 16u);
        cpa16(base + 3*TILE_B + doff[j], bl + moff, 16u);
      }
      CP_COMMIT();
      CP_WAIT(1);
    } else {
      CP_WAIT(0);
    }
    __syncthreads();

    uint32_t bA = sb + (uint32_t)(c&1)*BUF_B;
#pragma unroll
    for (int ks=0; ks<4; ks++){
      uint32_t ahr[2][4], alr[2][4];
#pragma unroll
      for (int t=0;t<2;t++){
        uint32_t aoff = (uint32_t)(arow + t*16)*128u + ((((uint32_t)(ks*2 + acb)) ^ (uint32_t)l7) * 16u);
        ldsm4(bA + 0*TILE_B + aoff, ahr[t]);
        ldsm4(bA + 1*TILE_B + aoff, alr[t]);
      }
#pragma unroll
      for (int p=0;p<2;p++){
        uint32_t bhr[4], blr[4];
        uint32_t nB = (uint32_t)(wn*32 + p*16 + bnp);
        uint32_t boff = nB*128u + ((((uint32_t)(ks*2 + bcb)) ^ (uint32_t)l7) * 16u);
        ldsm4(bA + 2*TILE_B + boff, bhr);
        ldsm4(bA + 3*TILE_B + boff, blr);
#pragma unroll
        for (int t=0;t<2;t++){
          mma16816(acc[t][2*p+0], ahr[t], bhr[0], bhr[1]);
          mma16816(acc[t][2*p+0], ahr[t], blr[0], blr[1]);
          mma16816(acc[t][2*p+0], alr[t], bhr[0], bhr[1]);
          mma16816(acc[t][2*p+1], ahr[t], bhr[2], bhr[3]);
          mma16816(acc[t][2*p+1], ahr[t], blr[2], blr[3]);
          mma16816(acc[t][2*p+1], alr[t], bhr[2], bhr[3]);
        }
      }
    }
    __syncthreads();
  }

  float* pz = part + (size_t)z*NN*CC;
#pragma unroll
  for (int t=0;t<2;t++){
    int r0 = row0 + wm*32 + t*16 + (lane>>2);
#pragma unroll
    for (int n=0;n<4;n++){
      int c0 = wn*32 + (n>>1)*16 + (n&1)*8 + (lane&3)*2;
      if (r0 < NN){
        float2 v; v.x = acc[t][n][0]; v.y = acc[t][n][1];
        *(float2*)(pz + (size_t)r0*CC + c0) = v;
      }
      if (r0 + 8 < NN){
        float2 v; v.x = acc[t][n][2]; v.y = acc[t][n][3];
        *(float2*)(pz + (size_t)(r0+8)*CC + c0) = v;
      }
    }
  }
}

// ---------------- elementwise / conversion ----------------
__global__ void k_initzero(){
  int idx = blockIdx.x*256 + threadIdx.x;
  const int per = M3P*CC/8;
  if (idx >= 8*per) return;
  int a = idx / per, off = idx - a*per;
  float4* p;
  switch(a){
    case 0: p = (float4*)g_hdbh; break;
    case 1: p = (float4*)g_hdbl; break;
    case 2: p = (float4*)g_ovbh; break;
    case 3: p = (float4*)g_ovbl; break;
    case 4: p = (float4*)g_hrbh; break;
    case 5: p = (float4*)g_hrbl; break;
    case 6: p = (float4*)g_hbh;  break;
    default: p = (float4*)g_hbl; break;
  }
  p[off] = make_float4(0.f,0.f,0.f,0.f);
}

__global__ void k_cvtw(const float* __restrict__ qw, const float* __restrict__ kw,
                       const float* __restrict__ vw, const float* __restrict__ ow,
                       const float* __restrict__ w2, const float* __restrict__ ow1){
  int i = blockIdx.x*256 + threadIdx.x;
  if (i >= 16*QTR) return;
  float v; bf* dh; bf* dl; int di;
  if (i < 9*QTR){
    int l = i / (3*QTR);
    int rem = i - l*3*QTR;
    int which = rem / QTR;
    int within = rem - which*QTR;
    const float* src = (which==0) ? qw : (which==1) ? kw : vw;
    v = src[(size_t)l*QTR + within];
    dh = g_wqh; dl = g_wql; di = i;
  } else if (i < 12*QTR){
    int j = i - 9*QTR;
    v = ow[j];
    dh = g_woh; dl = g_wol; di = j;
  } else if (i < 15*QTR){
    int j = i - 12*QTR;
    int lc = j >> 7, k = j & 127;
    v = w2[(size_t)lc*(2*CC) + k];
    dh = g_w2h; dl = g_w2l; di = j;
  } else {
    int j = i - 15*QTR;
    v = ow1[j];
    dh = g_wo1h; dl = g_wo1l; di = j;
  }
  bf h, lo; split_bf(v, h, lo);
  dh[di] = h; dl[di] = lo;
}

__global__ void k_adjconv(const float* __restrict__ adj){
  int row = blockIdx.x;
  const float* src = adj + (size_t)row*NN;
  bf* dh = g_adj_hi + (size_t)row*PADM;
  bf* dl = g_adj_lo + (size_t)row*PADM;
#pragma unroll
  for (int t=0; t<PADM/256; t++){
    int m = threadIdx.x + t*256;
    float v = (m < NN) ? src[m] : 0.f;
    bf h,l; split_bf(v,h,l);
    dh[m] = h; dl[m] = l;
  }
}

__global__ void k_wmsball(const float* __restrict__ tr, const float* __restrict__ cw)
{
  int idx = blockIdx.x*256 + threadIdx.x;
  if (idx >= LL*RR*CC*CC) return;
  int l = idx / (RR*CC*CC);
  int rem = idx - l*RR*CC*CC;
  int r = rem >> 14;
  int oc = rem & 16383;
  const float* base = tr + (((size_t)(l*RR + r)*KKc) << 14) + oc;
  float s = 0.f;
#pragma unroll
  for (int k=0;k<KKc;k++) s += base[(size_t)k << 14];
  float v = cw[l*RR + r] * s * (1.0f/KKc);
  bf h,lo; split_bf(v,h,lo);
  g_wmsh[idx] = h; g_wmsl[idx] = lo;
}

__global__ void __launch_bounds__(1024,1)
k_hpvec(const float* __restrict__ w1, const float* __restrict__ b1,
        const float* __restrict__ eb1, const float* __restrict__ w2,
        const float* __restrict__ b2, const float* __restrict__ eb2,
        const float* __restrict__ qb, const float* __restrict__ kb,
        const float* __restrict__ vb)
{
  extern __shared__ float sw[];
  float* s1 = sw;
  float* s2 = sw + CC*HPV_PITCH;
  float* hp = sw + 2*CC*HPV_PITCH;
  int tid = threadIdx.x;
  for (int i = tid; i < LL*3*CC; i += 1024){
    int l = i / (3*CC);
    int rem = i - l*3*CC;
    int which = rem >> 7, c = rem & 127;
    const float* s = (which==0) ? qb : (which==1) ? kb : vb;
    g_bqkv[i] = s[l*CC + c];
  }
  if (tid < CC) hp[tid] = 0.f;
  int c = tid >> 3, g = tid & 7;
  for (int l=0; l<LL; l++){
    __syncthreads();
    for (int j = tid; j < CC*CC/2; j += 1024){
      int cc = j >> 6;
      int k2 = (j & 63) << 1;
      float2 v1 = *(const float2*)(w1 + (size_t)l*QTR + cc*CC + k2);
      float2 v2 = *(const float2*)(w2 + ((size_t)(l*CC)+cc)*(2*CC) + CC + k2);
      *(float2*)(s1 + cc*HPV_PITCH + k2) = v1;
      *(float2*)(s2 + cc*HPV_PITCH + k2) = v2;
    }
    __syncthreads();
    float nh = 0.f, bv = 0.f;
#pragma unroll
    for (int kk=0; kk<16; kk++){
      int k = kk*8 + g;
      float hv = hp[k];
      nh += hv * s1[c*HPV_PITCH + k];
      bv += hv * s2[c*HPV_PITCH + k];
    }
#pragma unroll
    for (int o=4;o>0;o>>=1){
      nh += __shfl_xor_sync(0xffffffffu, nh, o);
      bv += __shfl_xor_sync(0xffffffffu, bv, o);
    }
    __syncthreads();
    if (g == 0){
      g_bv[l*CC+c] = bv + b2[l*CC+c] + eb2[l*CC+c];
      hp[c] = fmaxf(nh + b1[l*CC+c] + eb1[l*CC+c], 0.f);
    }
  }
}

__global__ void k_reduce(const float* __restrict__ convb, int l)
{
  int idx = blockIdx.x*256 + threadIdx.x;
  if (idx >= M3*CC) return;
  int b = idx / (NN*CC);
  int in = idx - b*NN*CC;
  int n = in / CC, c = in - n*CC;
  const float* p = g_part + (size_t)b*RR*NN*CC + in;
  float s = convb[l];
#pragma unroll
  for (int j=0;j<RR;j++) s += p[(size_t)j*NN*CC];
  s = fmaxf(s, 0.f);
  bf h,lo; split_bf(s,h,lo);
  size_t o = (size_t)(b*NP + n)*CC + c;
  g_hdbh[o] = h; g_hdbl[o] = lo;
}

__global__ void k_ret()
{
  int m = blockIdx.x, c = threadIdx.x;
  int b = m / NN;
  size_t mp = (size_t)(b*NP + (m - b*NN));
  const float* bp = g_qkv + mp*384;
  float q = bp[c], kk = bp[128+c], v = bp[256+c];
  float s = q*kk;
#pragma unroll
  for (int o=16;o>0;o>>=1) s += __shfl_xor_sync(0xffffffffu, s, o);
  float ov = s*v;
  bf h,lo; split_bf(ov,h,lo);
  g_ovbh[mp*128 + c] = h; g_ovbl[mp*128 + c] = lo;
}

__global__ void k_out2(const float* __restrict__ w, const float* __restrict__ bb,
                       float* __restrict__ out)
{
  int row = blockIdx.x, c = threadIdx.x;
  int b = row / NN;
  size_t mp = (size_t)(b*NP + (row - b*NN));
  float x = g_hmid[mp*128 + c];
  float s0 = x * w[c];
  float s1 = x * w[128 + c];
#pragma unroll
  for (int o=16;o>0;o>>=1){
    s0 += __shfl_xor_sync(0xffffffffu, s0, o);
    s1 += __shfl_xor_sync(0xffffffffu, s1, o);
  }
  __shared__ float sm[2][4];
  int wid = c >> 5;
  if ((c & 31) == 0){ sm[0][wid] = s0; sm[1][wid] = s1; }
  __syncthreads();
  if (c == 0) out[row*2 + 0] = sm[0][0]+sm[0][1]+sm[0][2]+sm[0][3] + bb[0];
  if (c == 1) out[row*2 + 1] = sm[1][0]+sm[1][1]+sm[1][2]+sm[1][3] + bb[1];
}

// ---------------- host ----------------
extern "C" void kernel_launch(void* const* d_in, const int* in_sizes, int n_in,
                              void* d_out, int out_size)
{
  (void)in_sizes; (void)n_in; (void)out_size;
  const float* x     = (const float*)d_in[0];
  const float* adj   = (const float*)d_in[1];
  const float* emb_w = (const float*)d_in[2];
  const float* emb_b = (const float*)d_in[3];
  const float* tr    = (const float*)d_in[5];
  const float* cw    = (const float*)d_in[6];
  const float* cb    = (const float*)d_in[7];
  const float* qw    = (const float*)d_in[8];
  const float* qb    = (const float*)d_in[9];
  const float* kw    = (const float*)d_in[10];
  const float* kb    = (const float*)d_in[11];
  const float* vw    = (const float*)d_in[12];
  const float* vb    = (const float*)d_in[13];
  const float* ow    = (const float*)d_in[14];
  const float* ob    = (const float*)d_in[15];
  const float* gg    = (const float*)d_in[16];
  const float* gb    = (const float*)d_in[17];
  const float* w1    = (const float*)d_in[18];
  const float* b1    = (const float*)d_in[19];
  const float* eb1   = (const float*)d_in[20];
  const float* w2    = (const float*)d_in[21];
  const float* b2    = (const float*)d_in[22];
  const float* eb2   = (const float*)d_in[23];
  const float* ow1   = (const float*)d_in[24];
  const float* ob1   = (const float*)d_in[25];
  const float* ow2   = (const float*)d_in[26];
  const float* ob2   = (const float*)d_in[27];
  float* out = (float*)d_out;

  float *p_part, *p_qkv, *p_hmid, *p_bqkv, *p_bv;
  bf *p_hbh,*p_hbl,*p_hdbh,*p_hdbl,*p_ovbh,*p_ovbl,*p_hrbh,*p_hrbl;
  bf *p_wqh,*p_wql,*p_woh,*p_wol,*p_w2h,*p_w2l,*p_wo1h,*p_wo1l,*p_wmsh,*p_wmsl;
  bf *p_hwth,*p_hwtl;
  cudaGetSymbolAddress((void**)&p_part, g_part);
  cudaGetSymbolAddress((void**)&p_qkv,  g_qkv);
  cudaGetSymbolAddress((void**)&p_hmid, g_hmid);
  cudaGetSymbolAddress((void**)&p_bqkv, g_bqkv);
  cudaGetSymbolAddress((void**)&p_bv,   g_bv);
  cudaGetSymbolAddress((void**)&p_hbh,  g_hbh);  cudaGetSymbolAddress((void**)&p_hbl,  g_hbl);
  cudaGetSymbolAddress((void**)&p_hdbh, g_hdbh); cudaGetSymbolAddress((void**)&p_hdbl, g_hdbl);
  cudaGetSymbolAddress((void**)&p_ovbh, g_ovbh); cudaGetSymbolAddress((void**)&p_ovbl, g_ovbl);
  cudaGetSymbolAddress((void**)&p_hrbh, g_hrbh); cudaGetSymbolAddress((void**)&p_hrbl, g_hrbl);
  cudaGetSymbolAddress((void**)&p_wqh,  g_wqh);  cudaGetSymbolAddress((void**)&p_wql,  g_wql);
  cudaGetSymbolAddress((void**)&p_woh,  g_woh);  cudaGetSymbolAddress((void**)&p_wol,  g_wol);
  cudaGetSymbolAddress((void**)&p_w2h,  g_w2h);  cudaGetSymbolAddress((void**)&p_w2l,  g_w2l);
  cudaGetSymbolAddress((void**)&p_wo1h, g_wo1h); cudaGetSymbolAddress((void**)&p_wo1l, g_wo1l);
  cudaGetSymbolAddress((void**)&p_wmsh, g_wmsh); cudaGetSymbolAddress((void**)&p_wmsl, g_wmsl);
  cudaGetSymbolAddress((void**)&p_hwth, g_hwt_hi); cudaGetSymbolAddress((void**)&p_hwtl, g_hwt_lo);

  cudaFuncSetAttribute(k_hmma_diff, cudaFuncAttributeMaxDynamicSharedMemorySize, SMEM_HMMA);
  cudaFuncSetAttribute(k_hgemm,     cudaFuncAttributeMaxDynamicSharedMemorySize, SMEM_HMMA);
  cudaFuncSetAttribute(k_hpvec,     cudaFuncAttributeMaxDynamicSharedMemorySize, SMEM_HPV);

  dim3 blk5(512);
  const int GRT = M3P/128;  // 24

  // (1) embed
  k_gemm<<<dim3((M3+63)/64,1,1), dim3(256)>>>(x + (TT-1)*DINc, TT*DINc, emb_w, DINc,
                                              p_hbh, p_hbl, M3, CC, DINc, emb_b);
  // (2) all layers' wms
  k_wmsball<<<(LL*RR*CC*CC + 255)/256, 256>>>(tr, cw);
  // (3) adjacency split
  k_adjconv<<<NB*RR*NN, 256>>>(adj);

  for (int l = 0; l < LL; l++){
    // (4 on l=0 -> PROFILED) hwt = wms_l @ h^T, bf hi/lo epilogue
    k_hgemm<<<dim3(RR, GRT, 1), blk5, SMEM_HMMA>>>(p_wmsh + (size_t)l*RR*QTR, p_wmsl + (size_t)l*RR*QTR,
                                                   p_hbh, p_hbl, CC,
                                                   nullptr, 0, p_hwth, p_hwtl, M3P,
                                                   nullptr, nullptr, 0, nullptr, nullptr);
    k_hmma_diff<<<dim3(NROWT,1,NB*RR), blk5, SMEM_HMMA>>>(p_part);
    k_reduce<<<(M3*CC + 255)/256, 256>>>(cb, l);

    if (l == 0){
      k_cvtw<<<(16*QTR + 255)/256, 256>>>(qw, kw, vw, ow, w2, ow1);
      k_hpvec<<<1, 1024, SMEM_HPV>>>(w1, b1, eb1, w2, b2, eb2, qb, kb, vb);
    }

    k_hgemm<<<dim3(GRT,3,1), blk5, SMEM_HMMA>>>(p_hdbh, p_hdbl,
                                                p_wqh + (size_t)l*3*QTR, p_wql + (size_t)l*3*QTR, CC,
                                                p_qkv, 3*CC, nullptr, nullptr, 0,
                                                p_bqkv + l*3*CC, nullptr, 0, nullptr, nullptr);
    k_ret<<<M3, 128>>>();
    k_hgemm<<<dim3(GRT,1,1), blk5, SMEM_HMMA>>>(p_ovbh, p_ovbl,
                                                p_woh + (size_t)l*QTR, p_wol + (size_t)l*QTR, CC,
                                                nullptr, 0, p_hrbh, p_hrbl, CC,
                                                ob + l*CC, nullptr, 0,
                                                gg + l*CC, gb + l*CC);
    k_hgemm<<<dim3(GRT,1,1), blk5, SMEM_HMMA>>>(p_hrbh, p_hrbl,
                                                p_w2h + (size_t)l*QTR, p_w2l + (size_t)l*QTR, CC,
                                                nullptr, 0, p_hbh, p_hbl, CC,
                                                p_bv + l*CC, nullptr, 1, nullptr, nullptr);
  }

  k_hgemm<<<dim3(GRT,1,1), blk5, SMEM_HMMA>>>(p_hbh, p_hbl, p_wo1h, p_wo1l, CC,
                                              p_hmid, CC, nullptr, nullptr, 0,
                                              ob1, nullptr, 1, nullptr, nullptr);
  k_out2<<<M3, 128>>>(ow2, ob2, out);
  k_initzero<<<(8*(M3P*CC/8) + 255)/256, 256>>>();
}